// round 13
// baseline (speedup 1.0000x reference)
#include <cuda_runtime.h>
#include <cuda_bf16.h>
#include <cstdint>
#include <math.h>

#define NVOX 262144              // 64*64*64
#define NN ((size_t)NVOX)

// ---- scratch (device globals; no allocations allowed) ----
__device__ float g_qkv[288 * NVOX];            // qkv after 1x1 conv
__device__ float g_dw [192 * NVOX];            // q,k after depthwise conv (fp32)
__device__ __nv_bfloat16 g_vh[96 * NVOX];      // v after dwconv, bf16 hi
__device__ __nv_bfloat16 g_vl[96 * NVOX];      // v after dwconv, bf16 lo
__device__ float g_partial[6 * 128 * 288];     // per (head, chunk): 256 gram + 32 norms
__device__ float g_gram[6 * 288];              // reduced gram + norms
__device__ float g_meff[96 * 96];              // W_proj @ blockdiag(attn)

#define XS 136   // X smem stride (bf16 elems), 272B rows -> conflict-free ldmatrix

__device__ __forceinline__ unsigned smem_u32(const void* p) {
    return (unsigned)__cvta_generic_to_shared(p);
}
__device__ __forceinline__ void ldsm_x4(unsigned* r, unsigned addr) {
    asm volatile("ldmatrix.sync.aligned.m8n8.x4.shared.b16 {%0,%1,%2,%3}, [%4];"
                 : "=r"(r[0]), "=r"(r[1]), "=r"(r[2]), "=r"(r[3]) : "r"(addr));
}
__device__ __forceinline__ void ldsm_x4t(unsigned* r, unsigned addr) {
    asm volatile("ldmatrix.sync.aligned.m8n8.x4.trans.shared.b16 {%0,%1,%2,%3}, [%4];"
                 : "=r"(r[0]), "=r"(r[1]), "=r"(r[2]), "=r"(r[3]) : "r"(addr));
}
__device__ __forceinline__ void mma16816(float* c, const unsigned* a,
                                         unsigned b0, unsigned b1) {
    asm volatile(
        "mma.sync.aligned.m16n8k16.row.col.f32.bf16.bf16.f32 "
        "{%0,%1,%2,%3}, {%4,%5,%6,%7}, {%8,%9}, {%0,%1,%2,%3};\n"
        : "+f"(c[0]), "+f"(c[1]), "+f"(c[2]), "+f"(c[3])
        : "r"(a[0]), "r"(a[1]), "r"(a[2]), "r"(a[3]), "r"(b0), "r"(b1));
}
__device__ __forceinline__ unsigned pack_hi(float a, float b, unsigned& lo_out) {
    __nv_bfloat162 h = __floats2bfloat162_rn(a, b);
    float2 hf = __bfloat1622float2(h);
    __nv_bfloat162 l = __floats2bfloat162_rn(a - hf.x, b - hf.y);
    lo_out = *(unsigned*)&l;
    return *(unsigned*)&h;
}

// =====================================================================
// A-fragment prep (fp32 W row-pair -> bf16 hi/lo register frags)
// =====================================================================
__device__ __forceinline__ void a_frags(const float* __restrict__ wr0,
                                        const float* __restrict__ wr1, int tt,
                                        unsigned Ah[6][4], unsigned Al[6][4]) {
#pragma unroll
    for (int kc = 0; kc < 6; kc++) {
        float2 w00 = *(const float2*)(wr0 + kc * 16 + tt * 2);
        float2 w10 = *(const float2*)(wr1 + kc * 16 + tt * 2);
        float2 w01 = *(const float2*)(wr0 + kc * 16 + tt * 2 + 8);
        float2 w11 = *(const float2*)(wr1 + kc * 16 + tt * 2 + 8);
        Ah[kc][0] = pack_hi(w00.x, w00.y, Al[kc][0]);
        Ah[kc][1] = pack_hi(w10.x, w10.y, Al[kc][1]);
        Ah[kc][2] = pack_hi(w01.x, w01.y, Al[kc][2]);
        Ah[kc][3] = pack_hi(w11.x, w11.y, Al[kc][3]);
    }
}

// =====================================================================
// MMA compute on one 96x128 X tile (interleaved accumulators)
// =====================================================================
__device__ __forceinline__ void mma_compute(const __nv_bfloat16* Xh, const __nv_bfloat16* Xl,
                                            const unsigned Ah[6][4], const unsigned Al[6][4],
                                            float* __restrict__ Yo, size_t nb,
                                            int m0, int lane) {
    const int g = lane >> 2, tt = lane & 3;
    const int bl = lane & 15;
    const int bcol = (lane >> 4) << 3;

    float acc[16][4];
#pragma unroll
    for (int nf = 0; nf < 16; nf++)
#pragma unroll
        for (int j = 0; j < 4; j++) acc[nf][j] = 0.f;

#pragma unroll
    for (int kc = 0; kc < 6; kc++) {
        const unsigned ah = smem_u32(&Xh[(kc * 16 + bl) * XS + bcol]);
        const unsigned al = smem_u32(&Xl[(kc * 16 + bl) * XS + bcol]);
#pragma unroll
        for (int nfp = 0; nfp < 8; nfp++) {
            unsigned bh[4], blo[4];
            ldsm_x4t(bh,  ah + nfp * 32);
            ldsm_x4t(blo, al + nfp * 32);
            mma16816(acc[2 * nfp],     Ah[kc], bh[0],  bh[1]);
            mma16816(acc[2 * nfp + 1], Ah[kc], bh[2],  bh[3]);
            mma16816(acc[2 * nfp],     Ah[kc], blo[0], blo[1]);
            mma16816(acc[2 * nfp + 1], Ah[kc], blo[2], blo[3]);
            mma16816(acc[2 * nfp],     Al[kc], bh[0],  bh[1]);
            mma16816(acc[2 * nfp + 1], Al[kc], bh[2],  bh[3]);
        }
    }

#pragma unroll
    for (int nf = 0; nf < 16; nf++) {
        float* y0 = Yo + (size_t)(m0 + g) * NN + nb + nf * 8 + 2 * tt;
        *(float2*)y0 = make_float2(acc[nf][0], acc[nf][1]);
        float* y1 = Yo + (size_t)(m0 + g + 8) * NN + nb + nf * 8 + 2 * tt;
        *(float2*)y1 = make_float2(acc[nf][2], acc[nf][3]);
    }
}

// =====================================================================
// qkv GEMM: X tile fp32 -> hi/lo smem; 3 output tiles per block.
// 3 CTAs/SM pinned for latency hiding.
// =====================================================================
__global__ void __launch_bounds__(192, 3)
qkv_fused_kernel(const float* __restrict__ x, const float* __restrict__ wqkv) {
    extern __shared__ __nv_bfloat16 smb[];
    __nv_bfloat16* Xh = smb;
    __nv_bfloat16* Xl = smb + 96 * XS;

    const int t = threadIdx.x;
    const size_t nb = (size_t)blockIdx.x * 128;

    for (int i = t; i < 96 * 32; i += 192) {
        const int r = i >> 5, c = i & 31;
        float4 v = *(const float4*)(x + (size_t)r * NN + nb + c * 4);
        unsigned l0, l1;
        unsigned h0 = pack_hi(v.x, v.y, l0);
        unsigned h1 = pack_hi(v.z, v.w, l1);
        *(uint2*)&Xh[r * XS + c * 4] = make_uint2(h0, h1);
        *(uint2*)&Xl[r * XS + c * 4] = make_uint2(l0, l1);
    }
    __syncthreads();

    const int w = t >> 5, lane = t & 31;
    const int m0 = w * 16;
    const int tt = lane & 3;

#pragma unroll 1
    for (int ot = 0; ot < 3; ot++) {
        const float* wr0 = wqkv + (size_t)(ot * 96 + m0 + (lane >> 2)) * 96;
        unsigned Ah[6][4], Al[6][4];
        a_frags(wr0, wr0 + 8 * 96, tt, Ah, Al);
        mma_compute(Xh, Xl, Ah, Al, g_qkv + (size_t)ot * 96 * NN, nb, m0, lane);
    }
}

// =====================================================================
// proj GEMM: X tile loaded as PRE-CONVERTED bf16 hi/lo.
// =====================================================================
__global__ void __launch_bounds__(192, 3)
proj_gemm_kernel(float* __restrict__ out) {
    extern __shared__ __nv_bfloat16 smb[];
    __nv_bfloat16* Xh = smb;
    __nv_bfloat16* Xl = smb + 96 * XS;

    const int t = threadIdx.x;
    const size_t nb = (size_t)blockIdx.x * 128;

    for (int i = t; i < 96 * 16; i += 192) {
        const int r = i >> 4, c = i & 15;
        const size_t go = (size_t)r * NN + nb + c * 8;
        *(uint4*)&Xh[r * XS + c * 8] = *(const uint4*)&g_vh[go];
        *(uint4*)&Xl[r * XS + c * 8] = *(const uint4*)&g_vl[go];
    }
    __syncthreads();

    const int w = t >> 5, lane = t & 31;
    const int m0 = w * 16;
    const int tt = lane & 3;
    const float* wr0 = g_meff + (size_t)(m0 + (lane >> 2)) * 96;
    unsigned Ah[6][4], Al[6][4];
    a_frags(wr0, wr0 + 8 * 96, tt, Ah, Al);
    mma_compute(Xh, Xl, Ah, Al, out, nb, m0, lane);
}

// =====================================================================
// Depthwise 3x3x3 conv — scalar; v channels (c>=192) -> bf16 hi/lo.
// =====================================================================
__global__ void __launch_bounds__(256)
dwconv_kernel(const float* __restrict__ wdw, int c0) {
    const int c  = blockIdx.z + c0;
    const int z0 = blockIdx.y * 8;
    const int y0 = blockIdx.x * 16;

    __shared__ float s[10 * 18 * 68];

    float wk[27];
#pragma unroll
    for (int i = 0; i < 27; i++) wk[i] = __ldg(&wdw[c * 27 + i]);

    const float* inc = g_qkv + (size_t)c * NN;
    const int t = threadIdx.x;

    for (int pos = t; pos < 18 * 66; pos += 256) {
        const int iy = pos / 66, ix = pos % 66;
        const int gy = y0 - 1 + iy, gx = ix - 1;
        const bool vyx = ((unsigned)gy < 64u) & ((unsigned)gx < 64u);
        const float* col = inc + ((size_t)gy * 64 + gx);
#pragma unroll
        for (int iz = 0; iz < 10; iz++) {
            const int gz = z0 - 1 + iz;
            float v = 0.f;
            if (vyx && (unsigned)gz < 64u)
                v = col[(size_t)gz * 4096];
            s[(iz * 18 + iy) * 68 + ix] = v;
        }
    }
    __syncthreads();

    const int xx = t & 15;
    const int yy = t >> 4;
    const int x4 = xx * 4;

    float a[8][4];
#pragma unroll
    for (int z = 0; z < 8; z++)
#pragma unroll
        for (int j = 0; j < 4; j++) a[z][j] = 0.f;

#pragma unroll
    for (int p = 0; p < 10; p++) {
        float r[3][6];
#pragma unroll
        for (int ky = 0; ky < 3; ky++) {
            const float* row = &s[(p * 18 + yy + ky) * 68 + x4];
            float4 q  = *(const float4*)row;
            float2 q2 = *(const float2*)(row + 4);
            r[ky][0] = q.x;  r[ky][1] = q.y;  r[ky][2] = q.z;
            r[ky][3] = q.w;  r[ky][4] = q2.x; r[ky][5] = q2.y;
        }
#pragma unroll
        for (int kz = 0; kz < 3; kz++) {
            const int z = p - kz;
            if (z >= 0 && z < 8) {
#pragma unroll
                for (int ky = 0; ky < 3; ky++)
#pragma unroll
                    for (int kx = 0; kx < 3; kx++) {
                        const float wv = wk[kz * 9 + ky * 3 + kx];
#pragma unroll
                        for (int dx = 0; dx < 4; dx++)
                            a[z][dx] = fmaf(wv, r[ky][dx + kx], a[z][dx]);
                    }
            }
        }
    }

    if (c < 192) {
        float* outc = g_dw + (size_t)c * NN;
#pragma unroll
        for (int z = 0; z < 8; z++) {
            *(float4*)&outc[((size_t)(z0 + z) * 64 + (y0 + yy)) * 64 + x4] =
                make_float4(a[z][0], a[z][1], a[z][2], a[z][3]);
        }
    } else {
        const size_t vb = (size_t)(c - 192) * NN;
#pragma unroll
        for (int z = 0; z < 8; z++) {
            const size_t o = vb + ((size_t)(z0 + z) * 64 + (y0 + yy)) * 64 + x4;
            unsigned l0, l1;
            unsigned h0 = pack_hi(a[z][0], a[z][1], l0);
            unsigned h1 = pack_hi(a[z][2], a[z][3], l1);
            *(uint2*)&g_vh[o] = make_uint2(h0, h1);
            *(uint2*)&g_vl[o] = make_uint2(l0, l1);
        }
    }
}

// =====================================================================
// Per-head Gram via tensor cores (unchanged)
// =====================================================================
#define GS 136

__global__ void __launch_bounds__(256)
gram_kernel() {
    const int h = blockIdx.y, chunk = blockIdx.x;
    __shared__ __nv_bfloat16 Qh[16 * GS], Ql[16 * GS], Kh[16 * GS], Kl[16 * GS];
    __shared__ float red[8][256];

    const int t = threadIdx.x;
    const int lane = t & 31, w = t >> 5;
    const int row = t >> 3;
    const int i8  = t & 7;
    const int srow = row & 15;

    const float* nbase = g_dw + (size_t)16 * h * NN + (size_t)chunk * 2048;
    const float* src = (row < 16)
        ? nbase + (size_t)row * NN
        : nbase + (size_t)96 * NN + (size_t)(row - 16) * NN;
    __nv_bfloat16* Dh = (row < 16) ? Qh : Kh;
    __nv_bfloat16* Dl = (row < 16) ? Ql : Kl;

    const int arow = lane & 15;
    const int acol = (lane >> 4) << 3;
    const int bd   = (lane & 7) + ((lane >> 4) << 3);
    const int bko  = ((lane >> 3) & 1) << 3;

    float sq = 0.f;
    float C0[4] = {0.f, 0.f, 0.f, 0.f};
    float C1[4] = {0.f, 0.f, 0.f, 0.f};

    for (int tile = 0; tile < 16; tile++) {
        const int off = tile * 128;
#pragma unroll
        for (int j = 0; j < 4; j++) {
            const int n = off + j * 32 + i8 * 4;
            float4 v = *(const float4*)(src + n);
            unsigned l0, l1;
            unsigned h0 = pack_hi(v.x, v.y, l0);
            unsigned h1 = pack_hi(v.z, v.w, l1);
            const int p = srow * GS + j * 32 + i8 * 4;
            *(uint2*)&Dh[p] = make_uint2(h0, h1);
            *(uint2*)&Dl[p] = make_uint2(l0, l1);
            sq = fmaf(v.x, v.x, fmaf(v.y, v.y, fmaf(v.z, v.z, fmaf(v.w, v.w, sq))));
        }
        __syncthreads();

        unsigned Af[4], Alf[4], Bh[4], Bl[4];
        ldsm_x4(Af,  smem_u32(&Qh[arow * GS + w * 16 + acol]));
        ldsm_x4(Alf, smem_u32(&Ql[arow * GS + w * 16 + acol]));
        ldsm_x4(Bh,  smem_u32(&Kh[bd * GS + w * 16 + bko]));
        ldsm_x4(Bl,  smem_u32(&Kl[bd * GS + w * 16 + bko]));
        mma16816(C0, Af,  Bh[0], Bh[1]);
        mma16816(C1, Af,  Bh[2], Bh[3]);
        mma16816(C0, Af,  Bl[0], Bl[1]);
        mma16816(C1, Af,  Bl[2], Bl[3]);
        mma16816(C0, Alf, Bh[0], Bh[1]);
        mma16816(C1, Alf, Bh[2], Bh[3]);
        __syncthreads();
    }

    const int cr = lane >> 2, cc2 = (lane & 3) * 2;
    red[w][cr * 16 + cc2]           = C0[0];
    red[w][cr * 16 + cc2 + 1]       = C0[1];
    red[w][(cr + 8) * 16 + cc2]     = C0[2];
    red[w][(cr + 8) * 16 + cc2 + 1] = C0[3];
    red[w][cr * 16 + 8 + cc2]           = C1[0];
    red[w][cr * 16 + 8 + cc2 + 1]       = C1[1];
    red[w][(cr + 8) * 16 + 8 + cc2]     = C1[2];
    red[w][(cr + 8) * 16 + 8 + cc2 + 1] = C1[3];
    __syncthreads();

    float acc = 0.f;
#pragma unroll
    for (int ww = 0; ww < 8; ww++) acc += red[ww][t];
    const size_t pb = ((size_t)h * 128 + chunk) * 288;
    g_partial[pb + t] = acc;

    sq += __shfl_xor_sync(0xffffffff, sq, 1);
    sq += __shfl_xor_sync(0xffffffff, sq, 2);
    sq += __shfl_xor_sync(0xffffffff, sq, 4);
    if (i8 == 0) g_partial[pb + 256 + row] = sq;
}

__global__ void __launch_bounds__(256)
reduce_kernel() {
    const int h = blockIdx.x / 9, grp = blockIdx.x % 9;
    const int t = threadIdx.x;
    const int e = grp * 32 + (t & 31);
    const int sub = t >> 5;
    float s = 0.f;
    const int ch0 = sub * 16;
    for (int ch = ch0; ch < ch0 + 16; ch++)
        s += g_partial[((size_t)h * 128 + ch) * 288 + e];
    __shared__ float sm[256];
    sm[t] = s; __syncthreads();
    if (t < 128) sm[t] += sm[t + 128]; __syncthreads();
    if (t < 64)  sm[t] += sm[t + 64];  __syncthreads();
    if (t < 32)  g_gram[h * 288 + e] = sm[t] + sm[t + 32];
}

__global__ void __launch_bounds__(256)
finalize_kernel(const float* __restrict__ temp, const float* __restrict__ wproj) {
    __shared__ float A[6 * 256];
    __shared__ float qn[6 * 16], kn[6 * 16];
    __shared__ float attn[6 * 256];
    const int t = threadIdx.x;

    for (int e = t; e < 1536; e += 256) {
        const int h = e >> 8, idx = e & 255;
        A[e] = g_gram[h * 288 + idx];
    }
    if (t < 192) {
        const int h = t / 32, r = t % 32;
        float nv = fmaxf(sqrtf(g_gram[h * 288 + 256 + r]), 1e-12f);
        if (r < 16) qn[h * 16 + r] = nv;
        else        kn[h * 16 + (r - 16)] = nv;
    }
    __syncthreads();

    if (t < 96) {
        const int h = t >> 4, c = t & 15;
        const float tp = temp[h];
        float l[16];
        float mx = -1e30f;
#pragma unroll
        for (int d = 0; d < 16; d++) {
            float v = A[h * 256 + c * 16 + d] / (qn[h * 16 + c] * kn[h * 16 + d]) * tp;
            l[d] = v;
            mx = fmaxf(mx, v);
        }
        float ssum = 0.f;
#pragma unroll
        for (int d = 0; d < 16; d++) { l[d] = expf(l[d] - mx); ssum += l[d]; }
        const float inv = 1.f / ssum;
#pragma unroll
        for (int d = 0; d < 16; d++) attn[h * 256 + c * 16 + d] = l[d] * inv;
    }
    __syncthreads();

    for (int e = t; e < 9216; e += 256) {
        const int o = e / 96, g = e % 96;
        const int h = g >> 4, d = g & 15;
        float ssum = 0.f;
#pragma unroll
        for (int c = 0; c < 16; c++)
            ssum = fmaf(wproj[o * 96 + 16 * h + c], attn[h * 256 + c * 16 + d], ssum);
        g_meff[e] = ssum;
    }
}

// =====================================================================
extern "C" void kernel_launch(void* const* d_in, const int* in_sizes, int n_in,
                              void* d_out, int out_size) {
    const float* x     = (const float*)d_in[0];
    const float* wqkv  = (const float*)d_in[1];
    const float* wdw   = (const float*)d_in[2];
    const float* wproj = (const float*)d_in[3];
    const float* temp  = (const float*)d_in[4];
    float* out = (float*)d_out;

    const int SMEM_QKV = 2 * 96 * XS * 2;   // 52224 B
    cudaFuncSetAttribute(qkv_fused_kernel, cudaFuncAttributeMaxDynamicSharedMemorySize, SMEM_QKV);
    cudaFuncSetAttribute(proj_gemm_kernel, cudaFuncAttributeMaxDynamicSharedMemorySize, SMEM_QKV);

    // 1) qkv = Wqkv @ x — single launch, minimal wave tail
    qkv_fused_kernel<<<2048, 192, SMEM_QKV>>>(x, wqkv);
    // 2) depthwise 3x3x3 conv, two halves (v -> bf16 hi/lo)
    dwconv_kernel<<<dim3(4, 8, 144), 256>>>(wdw, 0);
    dwconv_kernel<<<dim3(4, 8, 144), 256>>>(wdw, 144);
    // 3) per-head Gram + norms via tensor cores (slot 3 = profiled)
    gram_kernel<<<dim3(128, 6), 256>>>();
    // 4) parallel reduction of partials
    reduce_kernel<<<54, 256>>>();
    // 5) softmax + fold projection
    finalize_kernel<<<1, 256>>>(temp, wproj);
    // 6) y = Meff @ v
    proj_gemm_kernel<<<2048, 192, SMEM_QKV>>>(out);
}

// round 14
// speedup vs baseline: 1.1429x; 1.1429x over previous
#include <cuda_runtime.h>
#include <cuda_bf16.h>
#include <cstdint>
#include <math.h>

#define NVOX 262144              // 64*64*64
#define NN ((size_t)NVOX)

// ---- scratch (device globals; no allocations allowed) ----
__device__ float g_qkv[288 * NVOX];            // qkv after 1x1 conv
__device__ float g_dw [192 * NVOX];            // q,k after depthwise conv (fp32)
__device__ __nv_bfloat16 g_vh[96 * NVOX];      // v after dwconv, bf16 hi
__device__ __nv_bfloat16 g_vl[96 * NVOX];      // v after dwconv, bf16 lo
__device__ float g_partial[6 * 128 * 288];     // per (head, chunk): 256 gram + 32 norms
__device__ float g_gram[6 * 288];              // reduced gram + norms
__device__ float g_meff[96 * 96];              // W_proj @ blockdiag(attn)

#define XS 136   // X smem stride (bf16 elems), 272B rows -> conflict-free ldmatrix

__device__ __forceinline__ unsigned smem_u32(const void* p) {
    return (unsigned)__cvta_generic_to_shared(p);
}
__device__ __forceinline__ void ldsm_x4(unsigned* r, unsigned addr) {
    asm volatile("ldmatrix.sync.aligned.m8n8.x4.shared.b16 {%0,%1,%2,%3}, [%4];"
                 : "=r"(r[0]), "=r"(r[1]), "=r"(r[2]), "=r"(r[3]) : "r"(addr));
}
__device__ __forceinline__ void ldsm_x4t(unsigned* r, unsigned addr) {
    asm volatile("ldmatrix.sync.aligned.m8n8.x4.trans.shared.b16 {%0,%1,%2,%3}, [%4];"
                 : "=r"(r[0]), "=r"(r[1]), "=r"(r[2]), "=r"(r[3]) : "r"(addr));
}
__device__ __forceinline__ void mma16816(float* c, const unsigned* a,
                                         unsigned b0, unsigned b1) {
    asm volatile(
        "mma.sync.aligned.m16n8k16.row.col.f32.bf16.bf16.f32 "
        "{%0,%1,%2,%3}, {%4,%5,%6,%7}, {%8,%9}, {%0,%1,%2,%3};\n"
        : "+f"(c[0]), "+f"(c[1]), "+f"(c[2]), "+f"(c[3])
        : "r"(a[0]), "r"(a[1]), "r"(a[2]), "r"(a[3]), "r"(b0), "r"(b1));
}
__device__ __forceinline__ unsigned pack_hi(float a, float b, unsigned& lo_out) {
    __nv_bfloat162 h = __floats2bfloat162_rn(a, b);
    float2 hf = __bfloat1622float2(h);
    __nv_bfloat162 l = __floats2bfloat162_rn(a - hf.x, b - hf.y);
    lo_out = *(unsigned*)&l;
    return *(unsigned*)&h;
}

// =====================================================================
// A-fragment prep (fp32 W row-pair -> bf16 hi/lo register frags)
// =====================================================================
__device__ __forceinline__ void a_frags(const float* __restrict__ wr0,
                                        const float* __restrict__ wr1, int tt,
                                        unsigned Ah[6][4], unsigned Al[6][4]) {
#pragma unroll
    for (int kc = 0; kc < 6; kc++) {
        float2 w00 = *(const float2*)(wr0 + kc * 16 + tt * 2);
        float2 w10 = *(const float2*)(wr1 + kc * 16 + tt * 2);
        float2 w01 = *(const float2*)(wr0 + kc * 16 + tt * 2 + 8);
        float2 w11 = *(const float2*)(wr1 + kc * 16 + tt * 2 + 8);
        Ah[kc][0] = pack_hi(w00.x, w00.y, Al[kc][0]);
        Ah[kc][1] = pack_hi(w10.x, w10.y, Al[kc][1]);
        Ah[kc][2] = pack_hi(w01.x, w01.y, Al[kc][2]);
        Ah[kc][3] = pack_hi(w11.x, w11.y, Al[kc][3]);
    }
}

// =====================================================================
// MMA compute on one 96x128 X tile (R10 ordering)
// =====================================================================
__device__ __forceinline__ void mma_compute(const __nv_bfloat16* Xh, const __nv_bfloat16* Xl,
                                            const unsigned Ah[6][4], const unsigned Al[6][4],
                                            float* __restrict__ Yo, size_t nb,
                                            int m0, int lane) {
    const int g = lane >> 2, tt = lane & 3;
    const int bl = lane & 15;
    const int bcol = (lane >> 4) << 3;

    float acc[16][4];
#pragma unroll
    for (int nf = 0; nf < 16; nf++)
#pragma unroll
        for (int j = 0; j < 4; j++) acc[nf][j] = 0.f;

#pragma unroll
    for (int kc = 0; kc < 6; kc++) {
        const unsigned ah = smem_u32(&Xh[(kc * 16 + bl) * XS + bcol]);
        const unsigned al = smem_u32(&Xl[(kc * 16 + bl) * XS + bcol]);
#pragma unroll
        for (int nfp = 0; nfp < 8; nfp++) {
            unsigned bh[4], blo[4];
            ldsm_x4t(bh,  ah + nfp * 32);
            ldsm_x4t(blo, al + nfp * 32);
            mma16816(acc[2 * nfp],     Ah[kc], bh[0],  bh[1]);
            mma16816(acc[2 * nfp],     Ah[kc], blo[0], blo[1]);
            mma16816(acc[2 * nfp],     Al[kc], bh[0],  bh[1]);
            mma16816(acc[2 * nfp + 1], Ah[kc], bh[2],  bh[3]);
            mma16816(acc[2 * nfp + 1], Ah[kc], blo[2], blo[3]);
            mma16816(acc[2 * nfp + 1], Al[kc], bh[2],  bh[3]);
        }
    }

#pragma unroll
    for (int nf = 0; nf < 16; nf++) {
        float* y0 = Yo + (size_t)(m0 + g) * NN + nb + nf * 8 + 2 * tt;
        *(float2*)y0 = make_float2(acc[nf][0], acc[nf][1]);
        float* y1 = Yo + (size_t)(m0 + g + 8) * NN + nb + nf * 8 + 2 * tt;
        *(float2*)y1 = make_float2(acc[nf][2], acc[nf][3]);
    }
}

// =====================================================================
// qkv GEMM (exact R10): X tile fp32 -> hi/lo smem; 3 output tiles.
// =====================================================================
__global__ void __launch_bounds__(192)
qkv_fused_kernel(const float* __restrict__ x, const float* __restrict__ wqkv, int bb) {
    extern __shared__ __nv_bfloat16 smb[];
    __nv_bfloat16* Xh = smb;
    __nv_bfloat16* Xl = smb + 96 * XS;

    const int t = threadIdx.x;
    const size_t nb = (size_t)(blockIdx.x + bb) * 128;

    for (int i = t; i < 96 * 32; i += 192) {
        const int r = i >> 5, c = i & 31;
        float4 v = *(const float4*)(x + (size_t)r * NN + nb + c * 4);
        unsigned l0, l1;
        unsigned h0 = pack_hi(v.x, v.y, l0);
        unsigned h1 = pack_hi(v.z, v.w, l1);
        *(uint2*)&Xh[r * XS + c * 4] = make_uint2(h0, h1);
        *(uint2*)&Xl[r * XS + c * 4] = make_uint2(l0, l1);
    }
    __syncthreads();

    const int w = t >> 5, lane = t & 31;
    const int m0 = w * 16;
    const int tt = lane & 3;

#pragma unroll 1
    for (int ot = 0; ot < 3; ot++) {
        const float* wr0 = wqkv + (size_t)(ot * 96 + m0 + (lane >> 2)) * 96;
        unsigned Ah[6][4], Al[6][4];
        a_frags(wr0, wr0 + 8 * 96, tt, Ah, Al);
        mma_compute(Xh, Xl, Ah, Al, g_qkv + (size_t)ot * 96 * NN, nb, m0, lane);
    }
}

// =====================================================================
// proj GEMM: 2 tiles per block, two smem buffers, A-frags built once.
// Loads are plain LDG/STS (L1-friendly); warps finishing tile-0 compute
// begin tile-1 loads before the barrier.
// =====================================================================
__global__ void __launch_bounds__(192)
proj_gemm_kernel(float* __restrict__ out) {
    extern __shared__ __nv_bfloat16 smb[];

    const int t = threadIdx.x;
    const size_t nb0 = (size_t)blockIdx.x * 256;

    const int w = t >> 5, lane = t & 31;
    const int m0 = w * 16;
    const int tt = lane & 3;

    // A-fragments from Meff, once per block
    const float* wr0 = g_meff + (size_t)(m0 + (lane >> 2)) * 96;
    unsigned Ah[6][4], Al[6][4];
    a_frags(wr0, wr0 + 8 * 96, tt, Ah, Al);

    // load tile 0 into buffer 0
    {
        __nv_bfloat16* Xh = smb;
        __nv_bfloat16* Xl = smb + 96 * XS;
        for (int i = t; i < 96 * 16; i += 192) {
            const int r = i >> 4, c = i & 15;
            const size_t go = (size_t)r * NN + nb0 + c * 8;
            *(uint4*)&Xh[r * XS + c * 8] = *(const uint4*)&g_vh[go];
            *(uint4*)&Xl[r * XS + c * 8] = *(const uint4*)&g_vl[go];
        }
    }
    __syncthreads();

    // compute tile 0
    mma_compute(smb, smb + 96 * XS, Ah, Al, out, nb0, m0, lane);

    // load tile 1 into buffer 1 (no barrier needed before: distinct buffer)
    {
        __nv_bfloat16* Xh = smb + 2 * 96 * XS;
        __nv_bfloat16* Xl = Xh + 96 * XS;
        const size_t nb1 = nb0 + 128;
        for (int i = t; i < 96 * 16; i += 192) {
            const int r = i >> 4, c = i & 15;
            const size_t go = (size_t)r * NN + nb1 + c * 8;
            *(uint4*)&Xh[r * XS + c * 8] = *(const uint4*)&g_vh[go];
            *(uint4*)&Xl[r * XS + c * 8] = *(const uint4*)&g_vl[go];
        }
    }
    __syncthreads();

    // compute tile 1
    mma_compute(smb + 2 * 96 * XS, smb + 3 * 96 * XS, Ah, Al, out, nb0 + 128, m0, lane);
}

// =====================================================================
// Depthwise 3x3x3 conv — scalar; v channels (c>=192) -> bf16 hi/lo.
// =====================================================================
__global__ void __launch_bounds__(256)
dwconv_kernel(const float* __restrict__ wdw, int c0) {
    const int c  = blockIdx.z + c0;
    const int z0 = blockIdx.y * 8;
    const int y0 = blockIdx.x * 16;

    __shared__ float s[10 * 18 * 68];

    float wk[27];
#pragma unroll
    for (int i = 0; i < 27; i++) wk[i] = __ldg(&wdw[c * 27 + i]);

    const float* inc = g_qkv + (size_t)c * NN;
    const int t = threadIdx.x;

    for (int pos = t; pos < 18 * 66; pos += 256) {
        const int iy = pos / 66, ix = pos % 66;
        const int gy = y0 - 1 + iy, gx = ix - 1;
        const bool vyx = ((unsigned)gy < 64u) & ((unsigned)gx < 64u);
        const float* col = inc + ((size_t)gy * 64 + gx);
#pragma unroll
        for (int iz = 0; iz < 10; iz++) {
            const int gz = z0 - 1 + iz;
            float v = 0.f;
            if (vyx && (unsigned)gz < 64u)
                v = col[(size_t)gz * 4096];
            s[(iz * 18 + iy) * 68 + ix] = v;
        }
    }
    __syncthreads();

    const int xx = t & 15;
    const int yy = t >> 4;
    const int x4 = xx * 4;

    float a[8][4];
#pragma unroll
    for (int z = 0; z < 8; z++)
#pragma unroll
        for (int j = 0; j < 4; j++) a[z][j] = 0.f;

#pragma unroll
    for (int p = 0; p < 10; p++) {
        float r[3][6];
#pragma unroll
        for (int ky = 0; ky < 3; ky++) {
            const float* row = &s[(p * 18 + yy + ky) * 68 + x4];
            float4 q  = *(const float4*)row;
            float2 q2 = *(const float2*)(row + 4);
            r[ky][0] = q.x;  r[ky][1] = q.y;  r[ky][2] = q.z;
            r[ky][3] = q.w;  r[ky][4] = q2.x; r[ky][5] = q2.y;
        }
#pragma unroll
        for (int kz = 0; kz < 3; kz++) {
            const int z = p - kz;
            if (z >= 0 && z < 8) {
#pragma unroll
                for (int ky = 0; ky < 3; ky++)
#pragma unroll
                    for (int kx = 0; kx < 3; kx++) {
                        const float wv = wk[kz * 9 + ky * 3 + kx];
#pragma unroll
                        for (int dx = 0; dx < 4; dx++)
                            a[z][dx] = fmaf(wv, r[ky][dx + kx], a[z][dx]);
                    }
            }
        }
    }

    if (c < 192) {
        float* outc = g_dw + (size_t)c * NN;
#pragma unroll
        for (int z = 0; z < 8; z++) {
            *(float4*)&outc[((size_t)(z0 + z) * 64 + (y0 + yy)) * 64 + x4] =
                make_float4(a[z][0], a[z][1], a[z][2], a[z][3]);
        }
    } else {
        const size_t vb = (size_t)(c - 192) * NN;
#pragma unroll
        for (int z = 0; z < 8; z++) {
            const size_t o = vb + ((size_t)(z0 + z) * 64 + (y0 + yy)) * 64 + x4;
            unsigned l0, l1;
            unsigned h0 = pack_hi(a[z][0], a[z][1], l0);
            unsigned h1 = pack_hi(a[z][2], a[z][3], l1);
            *(uint2*)&g_vh[o] = make_uint2(h0, h1);
            *(uint2*)&g_vl[o] = make_uint2(l0, l1);
        }
    }
}

// =====================================================================
// Per-head Gram via tensor cores (unchanged)
// =====================================================================
#define GS 136

__global__ void __launch_bounds__(256)
gram_kernel() {
    const int h = blockIdx.y, chunk = blockIdx.x;
    __shared__ __nv_bfloat16 Qh[16 * GS], Ql[16 * GS], Kh[16 * GS], Kl[16 * GS];
    __shared__ float red[8][256];

    const int t = threadIdx.x;
    const int lane = t & 31, w = t >> 5;
    const int row = t >> 3;
    const int i8  = t & 7;
    const int srow = row & 15;

    const float* nbase = g_dw + (size_t)16 * h * NN + (size_t)chunk * 2048;
    const float* src = (row < 16)
        ? nbase + (size_t)row * NN
        : nbase + (size_t)96 * NN + (size_t)(row - 16) * NN;
    __nv_bfloat16* Dh = (row < 16) ? Qh : Kh;
    __nv_bfloat16* Dl = (row < 16) ? Ql : Kl;

    const int arow = lane & 15;
    const int acol = (lane >> 4) << 3;
    const int bd   = (lane & 7) + ((lane >> 4) << 3);
    const int bko  = ((lane >> 3) & 1) << 3;

    float sq = 0.f;
    float C0[4] = {0.f, 0.f, 0.f, 0.f};
    float C1[4] = {0.f, 0.f, 0.f, 0.f};

    for (int tile = 0; tile < 16; tile++) {
        const int off = tile * 128;
#pragma unroll
        for (int j = 0; j < 4; j++) {
            const int n = off + j * 32 + i8 * 4;
            float4 v = *(const float4*)(src + n);
            unsigned l0, l1;
            unsigned h0 = pack_hi(v.x, v.y, l0);
            unsigned h1 = pack_hi(v.z, v.w, l1);
            const int p = srow * GS + j * 32 + i8 * 4;
            *(uint2*)&Dh[p] = make_uint2(h0, h1);
            *(uint2*)&Dl[p] = make_uint2(l0, l1);
            sq = fmaf(v.x, v.x, fmaf(v.y, v.y, fmaf(v.z, v.z, fmaf(v.w, v.w, sq))));
        }
        __syncthreads();

        unsigned Af[4], Alf[4], Bh[4], Bl[4];
        ldsm_x4(Af,  smem_u32(&Qh[arow * GS + w * 16 + acol]));
        ldsm_x4(Alf, smem_u32(&Ql[arow * GS + w * 16 + acol]));
        ldsm_x4(Bh,  smem_u32(&Kh[bd * GS + w * 16 + bko]));
        ldsm_x4(Bl,  smem_u32(&Kl[bd * GS + w * 16 + bko]));
        mma16816(C0, Af,  Bh[0], Bh[1]);
        mma16816(C1, Af,  Bh[2], Bh[3]);
        mma16816(C0, Af,  Bl[0], Bl[1]);
        mma16816(C1, Af,  Bl[2], Bl[3]);
        mma16816(C0, Alf, Bh[0], Bh[1]);
        mma16816(C1, Alf, Bh[2], Bh[3]);
        __syncthreads();
    }

    const int cr = lane >> 2, cc2 = (lane & 3) * 2;
    red[w][cr * 16 + cc2]           = C0[0];
    red[w][cr * 16 + cc2 + 1]       = C0[1];
    red[w][(cr + 8) * 16 + cc2]     = C0[2];
    red[w][(cr + 8) * 16 + cc2 + 1] = C0[3];
    red[w][cr * 16 + 8 + cc2]           = C1[0];
    red[w][cr * 16 + 8 + cc2 + 1]       = C1[1];
    red[w][(cr + 8) * 16 + 8 + cc2]     = C1[2];
    red[w][(cr + 8) * 16 + 8 + cc2 + 1] = C1[3];
    __syncthreads();

    float acc = 0.f;
#pragma unroll
    for (int ww = 0; ww < 8; ww++) acc += red[ww][t];
    const size_t pb = ((size_t)h * 128 + chunk) * 288;
    g_partial[pb + t] = acc;

    sq += __shfl_xor_sync(0xffffffff, sq, 1);
    sq += __shfl_xor_sync(0xffffffff, sq, 2);
    sq += __shfl_xor_sync(0xffffffff, sq, 4);
    if (i8 == 0) g_partial[pb + 256 + row] = sq;
}

__global__ void __launch_bounds__(256)
reduce_kernel() {
    const int h = blockIdx.x / 9, grp = blockIdx.x % 9;
    const int t = threadIdx.x;
    const int e = grp * 32 + (t & 31);
    const int sub = t >> 5;
    float s = 0.f;
    const int ch0 = sub * 16;
    for (int ch = ch0; ch < ch0 + 16; ch++)
        s += g_partial[((size_t)h * 128 + ch) * 288 + e];
    __shared__ float sm[256];
    sm[t] = s; __syncthreads();
    if (t < 128) sm[t] += sm[t + 128]; __syncthreads();
    if (t < 64)  sm[t] += sm[t + 64];  __syncthreads();
    if (t < 32)  g_gram[h * 288 + e] = sm[t] + sm[t + 32];
}

__global__ void __launch_bounds__(256)
finalize_kernel(const float* __restrict__ temp, const float* __restrict__ wproj) {
    __shared__ float A[6 * 256];
    __shared__ float qn[6 * 16], kn[6 * 16];
    __shared__ float attn[6 * 256];
    const int t = threadIdx.x;

    for (int e = t; e < 1536; e += 256) {
        const int h = e >> 8, idx = e & 255;
        A[e] = g_gram[h * 288 + idx];
    }
    if (t < 192) {
        const int h = t / 32, r = t % 32;
        float nv = fmaxf(sqrtf(g_gram[h * 288 + 256 + r]), 1e-12f);
        if (r < 16) qn[h * 16 + r] = nv;
        else        kn[h * 16 + (r - 16)] = nv;
    }
    __syncthreads();

    if (t < 96) {
        const int h = t >> 4, c = t & 15;
        const float tp = temp[h];
        float l[16];
        float mx = -1e30f;
#pragma unroll
        for (int d = 0; d < 16; d++) {
            float v = A[h * 256 + c * 16 + d] / (qn[h * 16 + c] * kn[h * 16 + d]) * tp;
            l[d] = v;
            mx = fmaxf(mx, v);
        }
        float ssum = 0.f;
#pragma unroll
        for (int d = 0; d < 16; d++) { l[d] = expf(l[d] - mx); ssum += l[d]; }
        const float inv = 1.f / ssum;
#pragma unroll
        for (int d = 0; d < 16; d++) attn[h * 256 + c * 16 + d] = l[d] * inv;
    }
    __syncthreads();

    for (int e = t; e < 9216; e += 256) {
        const int o = e / 96, g = e % 96;
        const int h = g >> 4, d = g & 15;
        float ssum = 0.f;
#pragma unroll
        for (int c = 0; c < 16; c++)
            ssum = fmaf(wproj[o * 96 + 16 * h + c], attn[h * 256 + c * 16 + d], ssum);
        g_meff[e] = ssum;
    }
}

// =====================================================================
extern "C" void kernel_launch(void* const* d_in, const int* in_sizes, int n_in,
                              void* d_out, int out_size) {
    const float* x     = (const float*)d_in[0];
    const float* wqkv  = (const float*)d_in[1];
    const float* wdw   = (const float*)d_in[2];
    const float* wproj = (const float*)d_in[3];
    const float* temp  = (const float*)d_in[4];
    float* out = (float*)d_out;

    const int SMEM_QKV  = 2 * 96 * XS * 2;       // 52224 B
    const int SMEM_PROJ = 2 * 2 * 96 * XS * 2;   // 104448 B (two buffers)
    cudaFuncSetAttribute(qkv_fused_kernel, cudaFuncAttributeMaxDynamicSharedMemorySize, SMEM_QKV);
    cudaFuncSetAttribute(proj_gemm_kernel, cudaFuncAttributeMaxDynamicSharedMemorySize, SMEM_PROJ);

    // 1) qkv = Wqkv @ x, 2 sub-launches (exact R10)
    qkv_fused_kernel<<<1024, 192, SMEM_QKV>>>(x, wqkv, 0);
    qkv_fused_kernel<<<1024, 192, SMEM_QKV>>>(x, wqkv, 1024);
    // 2) depthwise 3x3x3 conv, two halves (v -> bf16 hi/lo); slot 3 = profiled
    dwconv_kernel<<<dim3(4, 8, 144), 256>>>(wdw, 0);
    dwconv_kernel<<<dim3(4, 8, 144), 256>>>(wdw, 144);
    // 3) per-head Gram + norms via tensor cores
    gram_kernel<<<dim3(128, 6), 256>>>();
    // 4) parallel reduction of partials
    reduce_kernel<<<54, 256>>>();
    // 5) softmax + fold projection
    finalize_kernel<<<1, 256>>>(temp, wproj);
    // 6) y = Meff @ v — 2 tiles/block, A-frags amortized
    proj_gemm_kernel<<<1024, 192, SMEM_PROJ>>>(out);
}

// round 15
// speedup vs baseline: 1.2475x; 1.0916x over previous
#include <cuda_runtime.h>
#include <cuda_bf16.h>
#include <cstdint>
#include <math.h>

#define NVOX 262144              // 64*64*64
#define NN ((size_t)NVOX)

// ---- scratch (device globals; no allocations allowed) ----
__device__ float g_qkv[288 * NVOX];            // qkv after 1x1 conv
__device__ float g_dw [192 * NVOX];            // q,k after depthwise conv (fp32)
__device__ __nv_bfloat16 g_vh[96 * NVOX];      // v after dwconv, bf16 hi
__device__ __nv_bfloat16 g_vl[96 * NVOX];      // v after dwconv, bf16 lo
__device__ float g_partial[6 * 128 * 288];     // per (head, chunk): 256 gram + 32 norms
__device__ float g_gram[6 * 288];              // reduced gram + norms
__device__ float g_meff[96 * 96];              // W_proj @ blockdiag(attn)

#define XS 136   // proj X smem stride (bf16), 272B rows
#define XS2 72   // qkv 64-col X smem stride (bf16), 144B rows -> conflict-free

__device__ __forceinline__ unsigned smem_u32(const void* p) {
    return (unsigned)__cvta_generic_to_shared(p);
}
__device__ __forceinline__ void ldsm_x4(unsigned* r, unsigned addr) {
    asm volatile("ldmatrix.sync.aligned.m8n8.x4.shared.b16 {%0,%1,%2,%3}, [%4];"
                 : "=r"(r[0]), "=r"(r[1]), "=r"(r[2]), "=r"(r[3]) : "r"(addr));
}
__device__ __forceinline__ void ldsm_x4t(unsigned* r, unsigned addr) {
    asm volatile("ldmatrix.sync.aligned.m8n8.x4.trans.shared.b16 {%0,%1,%2,%3}, [%4];"
                 : "=r"(r[0]), "=r"(r[1]), "=r"(r[2]), "=r"(r[3]) : "r"(addr));
}
__device__ __forceinline__ void mma16816(float* c, const unsigned* a,
                                         unsigned b0, unsigned b1) {
    asm volatile(
        "mma.sync.aligned.m16n8k16.row.col.f32.bf16.bf16.f32 "
        "{%0,%1,%2,%3}, {%4,%5,%6,%7}, {%8,%9}, {%0,%1,%2,%3};\n"
        : "+f"(c[0]), "+f"(c[1]), "+f"(c[2]), "+f"(c[3])
        : "r"(a[0]), "r"(a[1]), "r"(a[2]), "r"(a[3]), "r"(b0), "r"(b1));
}
__device__ __forceinline__ unsigned pack_hi(float a, float b, unsigned& lo_out) {
    __nv_bfloat162 h = __floats2bfloat162_rn(a, b);
    float2 hf = __bfloat1622float2(h);
    __nv_bfloat162 l = __floats2bfloat162_rn(a - hf.x, b - hf.y);
    lo_out = *(unsigned*)&l;
    return *(unsigned*)&h;
}

// =====================================================================
// A-fragment prep (fp32 W row-pair -> bf16 hi/lo register frags)
// =====================================================================
__device__ __forceinline__ void a_frags(const float* __restrict__ wr0,
                                        const float* __restrict__ wr1, int tt,
                                        unsigned Ah[6][4], unsigned Al[6][4]) {
#pragma unroll
    for (int kc = 0; kc < 6; kc++) {
        float2 w00 = *(const float2*)(wr0 + kc * 16 + tt * 2);
        float2 w10 = *(const float2*)(wr1 + kc * 16 + tt * 2);
        float2 w01 = *(const float2*)(wr0 + kc * 16 + tt * 2 + 8);
        float2 w11 = *(const float2*)(wr1 + kc * 16 + tt * 2 + 8);
        Ah[kc][0] = pack_hi(w00.x, w00.y, Al[kc][0]);
        Ah[kc][1] = pack_hi(w10.x, w10.y, Al[kc][1]);
        Ah[kc][2] = pack_hi(w01.x, w01.y, Al[kc][2]);
        Ah[kc][3] = pack_hi(w11.x, w11.y, Al[kc][3]);
    }
}

// =====================================================================
// qkv GEMM — 64-col X tiles (26KB smem), 3 CTAs/SM, W stays L1-resident.
// =====================================================================
__global__ void __launch_bounds__(192, 3)
qkv_fused_kernel(const float* __restrict__ x, const float* __restrict__ wqkv) {
    extern __shared__ __nv_bfloat16 smb[];
    __nv_bfloat16* Xh = smb;
    __nv_bfloat16* Xl = smb + 96 * XS2;

    const int t = threadIdx.x;
    const size_t nb = (size_t)blockIdx.x * 64;

    for (int i = t; i < 96 * 16; i += 192) {
        const int r = i >> 4, c = i & 15;
        float4 v = *(const float4*)(x + (size_t)r * NN + nb + c * 4);
        unsigned l0, l1;
        unsigned h0 = pack_hi(v.x, v.y, l0);
        unsigned h1 = pack_hi(v.z, v.w, l1);
        *(uint2*)&Xh[r * XS2 + c * 4] = make_uint2(h0, h1);
        *(uint2*)&Xl[r * XS2 + c * 4] = make_uint2(l0, l1);
    }
    __syncthreads();

    const int w = t >> 5, lane = t & 31;
    const int m0 = w * 16;
    const int g = lane >> 2, tt = lane & 3;
    const int bl = lane & 15;
    const int bcol = (lane >> 4) << 3;

#pragma unroll 1
    for (int ot = 0; ot < 3; ot++) {
        const float* wr0 = wqkv + (size_t)(ot * 96 + m0 + g) * 96;
        unsigned Ah[6][4], Al[6][4];
        a_frags(wr0, wr0 + 8 * 96, tt, Ah, Al);

        float acc[8][4];
#pragma unroll
        for (int nf = 0; nf < 8; nf++)
#pragma unroll
            for (int j = 0; j < 4; j++) acc[nf][j] = 0.f;

#pragma unroll
        for (int kc = 0; kc < 6; kc++) {
            const unsigned ah = smem_u32(&Xh[(kc * 16 + bl) * XS2 + bcol]);
            const unsigned al = smem_u32(&Xl[(kc * 16 + bl) * XS2 + bcol]);
#pragma unroll
            for (int nfp = 0; nfp < 4; nfp++) {
                unsigned bh[4], blo[4];
                ldsm_x4t(bh,  ah + nfp * 32);
                ldsm_x4t(blo, al + nfp * 32);
                mma16816(acc[2 * nfp],     Ah[kc], bh[0],  bh[1]);
                mma16816(acc[2 * nfp],     Ah[kc], blo[0], blo[1]);
                mma16816(acc[2 * nfp],     Al[kc], bh[0],  bh[1]);
                mma16816(acc[2 * nfp + 1], Ah[kc], bh[2],  bh[3]);
                mma16816(acc[2 * nfp + 1], Ah[kc], blo[2], blo[3]);
                mma16816(acc[2 * nfp + 1], Al[kc], bh[2],  bh[3]);
            }
        }

        float* Yo = g_qkv + (size_t)ot * 96 * NN;
#pragma unroll
        for (int nf = 0; nf < 8; nf++) {
            float* y0 = Yo + (size_t)(m0 + g) * NN + nb + nf * 8 + 2 * tt;
            *(float2*)y0 = make_float2(acc[nf][0], acc[nf][1]);
            float* y1 = Yo + (size_t)(m0 + g + 8) * NN + nb + nf * 8 + 2 * tt;
            *(float2*)y1 = make_float2(acc[nf][2], acc[nf][3]);
        }
    }
}

// =====================================================================
// proj GEMM (R14 form): 2 tiles/block, two buffers, A-frags once.
// =====================================================================
__device__ __forceinline__ void mma_compute(const __nv_bfloat16* Xh, const __nv_bfloat16* Xl,
                                            const unsigned Ah[6][4], const unsigned Al[6][4],
                                            float* __restrict__ Yo, size_t nb,
                                            int m0, int lane) {
    const int g = lane >> 2, tt = lane & 3;
    const int bl = lane & 15;
    const int bcol = (lane >> 4) << 3;

    float acc[16][4];
#pragma unroll
    for (int nf = 0; nf < 16; nf++)
#pragma unroll
        for (int j = 0; j < 4; j++) acc[nf][j] = 0.f;

#pragma unroll
    for (int kc = 0; kc < 6; kc++) {
        const unsigned ah = smem_u32(&Xh[(kc * 16 + bl) * XS + bcol]);
        const unsigned al = smem_u32(&Xl[(kc * 16 + bl) * XS + bcol]);
#pragma unroll
        for (int nfp = 0; nfp < 8; nfp++) {
            unsigned bh[4], blo[4];
            ldsm_x4t(bh,  ah + nfp * 32);
            ldsm_x4t(blo, al + nfp * 32);
            mma16816(acc[2 * nfp],     Ah[kc], bh[0],  bh[1]);
            mma16816(acc[2 * nfp],     Ah[kc], blo[0], blo[1]);
            mma16816(acc[2 * nfp],     Al[kc], bh[0],  bh[1]);
            mma16816(acc[2 * nfp + 1], Ah[kc], bh[2],  bh[3]);
            mma16816(acc[2 * nfp + 1], Ah[kc], blo[2], blo[3]);
            mma16816(acc[2 * nfp + 1], Al[kc], bh[2],  bh[3]);
        }
    }

#pragma unroll
    for (int nf = 0; nf < 16; nf++) {
        float* y0 = Yo + (size_t)(m0 + g) * NN + nb + nf * 8 + 2 * tt;
        *(float2*)y0 = make_float2(acc[nf][0], acc[nf][1]);
        float* y1 = Yo + (size_t)(m0 + g + 8) * NN + nb + nf * 8 + 2 * tt;
        *(float2*)y1 = make_float2(acc[nf][2], acc[nf][3]);
    }
}

__global__ void __launch_bounds__(192)
proj_gemm_kernel(float* __restrict__ out) {
    extern __shared__ __nv_bfloat16 smb[];

    const int t = threadIdx.x;
    const size_t nb0 = (size_t)blockIdx.x * 256;

    const int w = t >> 5, lane = t & 31;
    const int m0 = w * 16;
    const int tt = lane & 3;

    const float* wr0 = g_meff + (size_t)(m0 + (lane >> 2)) * 96;
    unsigned Ah[6][4], Al[6][4];
    a_frags(wr0, wr0 + 8 * 96, tt, Ah, Al);

    {
        __nv_bfloat16* Xh = smb;
        __nv_bfloat16* Xl = smb + 96 * XS;
        for (int i = t; i < 96 * 16; i += 192) {
            const int r = i >> 4, c = i & 15;
            const size_t go = (size_t)r * NN + nb0 + c * 8;
            *(uint4*)&Xh[r * XS + c * 8] = *(const uint4*)&g_vh[go];
            *(uint4*)&Xl[r * XS + c * 8] = *(const uint4*)&g_vl[go];
        }
    }
    __syncthreads();
    mma_compute(smb, smb + 96 * XS, Ah, Al, out, nb0, m0, lane);

    {
        __nv_bfloat16* Xh = smb + 2 * 96 * XS;
        __nv_bfloat16* Xl = Xh + 96 * XS;
        const size_t nb1 = nb0 + 128;
        for (int i = t; i < 96 * 16; i += 192) {
            const int r = i >> 4, c = i & 15;
            const size_t go = (size_t)r * NN + nb1 + c * 8;
            *(uint4*)&Xh[r * XS + c * 8] = *(const uint4*)&g_vh[go];
            *(uint4*)&Xl[r * XS + c * 8] = *(const uint4*)&g_vl[go];
        }
    }
    __syncthreads();
    mma_compute(smb + 2 * 96 * XS, smb + 3 * 96 * XS, Ah, Al, out, nb0 + 128, m0, lane);
}

// =====================================================================
// Depthwise 3x3x3 conv — scalar; v channels (c>=192) -> bf16 hi/lo.
// =====================================================================
__global__ void __launch_bounds__(256)
dwconv_kernel(const float* __restrict__ wdw, int c0) {
    const int c  = blockIdx.z + c0;
    const int z0 = blockIdx.y * 8;
    const int y0 = blockIdx.x * 16;

    __shared__ float s[10 * 18 * 68];

    float wk[27];
#pragma unroll
    for (int i = 0; i < 27; i++) wk[i] = __ldg(&wdw[c * 27 + i]);

    const float* inc = g_qkv + (size_t)c * NN;
    const int t = threadIdx.x;

    for (int pos = t; pos < 18 * 66; pos += 256) {
        const int iy = pos / 66, ix = pos % 66;
        const int gy = y0 - 1 + iy, gx = ix - 1;
        const bool vyx = ((unsigned)gy < 64u) & ((unsigned)gx < 64u);
        const float* col = inc + ((size_t)gy * 64 + gx);
#pragma unroll
        for (int iz = 0; iz < 10; iz++) {
            const int gz = z0 - 1 + iz;
            float v = 0.f;
            if (vyx && (unsigned)gz < 64u)
                v = col[(size_t)gz * 4096];
            s[(iz * 18 + iy) * 68 + ix] = v;
        }
    }
    __syncthreads();

    const int xx = t & 15;
    const int yy = t >> 4;
    const int x4 = xx * 4;

    float a[8][4];
#pragma unroll
    for (int z = 0; z < 8; z++)
#pragma unroll
        for (int j = 0; j < 4; j++) a[z][j] = 0.f;

#pragma unroll
    for (int p = 0; p < 10; p++) {
        float r[3][6];
#pragma unroll
        for (int ky = 0; ky < 3; ky++) {
            const float* row = &s[(p * 18 + yy + ky) * 68 + x4];
            float4 q  = *(const float4*)row;
            float2 q2 = *(const float2*)(row + 4);
            r[ky][0] = q.x;  r[ky][1] = q.y;  r[ky][2] = q.z;
            r[ky][3] = q.w;  r[ky][4] = q2.x; r[ky][5] = q2.y;
        }
#pragma unroll
        for (int kz = 0; kz < 3; kz++) {
            const int z = p - kz;
            if (z >= 0 && z < 8) {
#pragma unroll
                for (int ky = 0; ky < 3; ky++)
#pragma unroll
                    for (int kx = 0; kx < 3; kx++) {
                        const float wv = wk[kz * 9 + ky * 3 + kx];
#pragma unroll
                        for (int dx = 0; dx < 4; dx++)
                            a[z][dx] = fmaf(wv, r[ky][dx + kx], a[z][dx]);
                    }
            }
        }
    }

    if (c < 192) {
        float* outc = g_dw + (size_t)c * NN;
#pragma unroll
        for (int z = 0; z < 8; z++) {
            *(float4*)&outc[((size_t)(z0 + z) * 64 + (y0 + yy)) * 64 + x4] =
                make_float4(a[z][0], a[z][1], a[z][2], a[z][3]);
        }
    } else {
        const size_t vb = (size_t)(c - 192) * NN;
#pragma unroll
        for (int z = 0; z < 8; z++) {
            const size_t o = vb + ((size_t)(z0 + z) * 64 + (y0 + yy)) * 64 + x4;
            unsigned l0, l1;
            unsigned h0 = pack_hi(a[z][0], a[z][1], l0);
            unsigned h1 = pack_hi(a[z][2], a[z][3], l1);
            *(uint2*)&g_vh[o] = make_uint2(h0, h1);
            *(uint2*)&g_vl[o] = make_uint2(l0, l1);
        }
    }
}

// =====================================================================
// Per-head Gram via tensor cores (unchanged)
// =====================================================================
#define GS 136

__global__ void __launch_bounds__(256)
gram_kernel() {
    const int h = blockIdx.y, chunk = blockIdx.x;
    __shared__ __nv_bfloat16 Qh[16 * GS], Ql[16 * GS], Kh[16 * GS], Kl[16 * GS];
    __shared__ float red[8][256];

    const int t = threadIdx.x;
    const int lane = t & 31, w = t >> 5;
    const int row = t >> 3;
    const int i8  = t & 7;
    const int srow = row & 15;

    const float* nbase = g_dw + (size_t)16 * h * NN + (size_t)chunk * 2048;
    const float* src = (row < 16)
        ? nbase + (size_t)row * NN
        : nbase + (size_t)96 * NN + (size_t)(row - 16) * NN;
    __nv_bfloat16* Dh = (row < 16) ? Qh : Kh;
    __nv_bfloat16* Dl = (row < 16) ? Ql : Kl;

    const int arow = lane & 15;
    const int acol = (lane >> 4) << 3;
    const int bd   = (lane & 7) + ((lane >> 4) << 3);
    const int bko  = ((lane >> 3) & 1) << 3;

    float sq = 0.f;
    float C0[4] = {0.f, 0.f, 0.f, 0.f};
    float C1[4] = {0.f, 0.f, 0.f, 0.f};

    for (int tile = 0; tile < 16; tile++) {
        const int off = tile * 128;
#pragma unroll
        for (int j = 0; j < 4; j++) {
            const int n = off + j * 32 + i8 * 4;
            float4 v = *(const float4*)(src + n);
            unsigned l0, l1;
            unsigned h0 = pack_hi(v.x, v.y, l0);
            unsigned h1 = pack_hi(v.z, v.w, l1);
            const int p = srow * GS + j * 32 + i8 * 4;
            *(uint2*)&Dh[p] = make_uint2(h0, h1);
            *(uint2*)&Dl[p] = make_uint2(l0, l1);
            sq = fmaf(v.x, v.x, fmaf(v.y, v.y, fmaf(v.z, v.z, fmaf(v.w, v.w, sq))));
        }
        __syncthreads();

        unsigned Af[4], Alf[4], Bh[4], Bl[4];
        ldsm_x4(Af,  smem_u32(&Qh[arow * GS + w * 16 + acol]));
        ldsm_x4(Alf, smem_u32(&Ql[arow * GS + w * 16 + acol]));
        ldsm_x4(Bh,  smem_u32(&Kh[bd * GS + w * 16 + bko]));
        ldsm_x4(Bl,  smem_u32(&Kl[bd * GS + w * 16 + bko]));
        mma16816(C0, Af,  Bh[0], Bh[1]);
        mma16816(C1, Af,  Bh[2], Bh[3]);
        mma16816(C0, Af,  Bl[0], Bl[1]);
        mma16816(C1, Af,  Bl[2], Bl[3]);
        mma16816(C0, Alf, Bh[0], Bh[1]);
        mma16816(C1, Alf, Bh[2], Bh[3]);
        __syncthreads();
    }

    const int cr = lane >> 2, cc2 = (lane & 3) * 2;
    red[w][cr * 16 + cc2]           = C0[0];
    red[w][cr * 16 + cc2 + 1]       = C0[1];
    red[w][(cr + 8) * 16 + cc2]     = C0[2];
    red[w][(cr + 8) * 16 + cc2 + 1] = C0[3];
    red[w][cr * 16 + 8 + cc2]           = C1[0];
    red[w][cr * 16 + 8 + cc2 + 1]       = C1[1];
    red[w][(cr + 8) * 16 + 8 + cc2]     = C1[2];
    red[w][(cr + 8) * 16 + 8 + cc2 + 1] = C1[3];
    __syncthreads();

    float acc = 0.f;
#pragma unroll
    for (int ww = 0; ww < 8; ww++) acc += red[ww][t];
    const size_t pb = ((size_t)h * 128 + chunk) * 288;
    g_partial[pb + t] = acc;

    sq += __shfl_xor_sync(0xffffffff, sq, 1);
    sq += __shfl_xor_sync(0xffffffff, sq, 2);
    sq += __shfl_xor_sync(0xffffffff, sq, 4);
    if (i8 == 0) g_partial[pb + 256 + row] = sq;
}

__global__ void __launch_bounds__(256)
reduce_kernel() {
    const int h = blockIdx.x / 9, grp = blockIdx.x % 9;
    const int t = threadIdx.x;
    const int e = grp * 32 + (t & 31);
    const int sub = t >> 5;
    float s = 0.f;
    const int ch0 = sub * 16;
    for (int ch = ch0; ch < ch0 + 16; ch++)
        s += g_partial[((size_t)h * 128 + ch) * 288 + e];
    __shared__ float sm[256];
    sm[t] = s; __syncthreads();
    if (t < 128) sm[t] += sm[t + 128]; __syncthreads();
    if (t < 64)  sm[t] += sm[t + 64];  __syncthreads();
    if (t < 32)  g_gram[h * 288 + e] = sm[t] + sm[t + 32];
}

__global__ void __launch_bounds__(256)
finalize_kernel(const float* __restrict__ temp, const float* __restrict__ wproj) {
    __shared__ float A[6 * 256];
    __shared__ float qn[6 * 16], kn[6 * 16];
    __shared__ float attn[6 * 256];
    const int t = threadIdx.x;

    for (int e = t; e < 1536; e += 256) {
        const int h = e >> 8, idx = e & 255;
        A[e] = g_gram[h * 288 + idx];
    }
    if (t < 192) {
        const int h = t / 32, r = t % 32;
        float nv = fmaxf(sqrtf(g_gram[h * 288 + 256 + r]), 1e-12f);
        if (r < 16) qn[h * 16 + r] = nv;
        else        kn[h * 16 + (r - 16)] = nv;
    }
    __syncthreads();

    if (t < 96) {
        const int h = t >> 4, c = t & 15;
        const float tp = temp[h];
        float l[16];
        float mx = -1e30f;
#pragma unroll
        for (int d = 0; d < 16; d++) {
            float v = A[h * 256 + c * 16 + d] / (qn[h * 16 + c] * kn[h * 16 + d]) * tp;
            l[d] = v;
            mx = fmaxf(mx, v);
        }
        float ssum = 0.f;
#pragma unroll
        for (int d = 0; d < 16; d++) { l[d] = expf(l[d] - mx); ssum += l[d]; }
        const float inv = 1.f / ssum;
#pragma unroll
        for (int d = 0; d < 16; d++) attn[h * 256 + c * 16 + d] = l[d] * inv;
    }
    __syncthreads();

    for (int e = t; e < 9216; e += 256) {
        const int o = e / 96, g = e % 96;
        const int h = g >> 4, d = g & 15;
        float ssum = 0.f;
#pragma unroll
        for (int c = 0; c < 16; c++)
            ssum = fmaf(wproj[o * 96 + 16 * h + c], attn[h * 256 + c * 16 + d], ssum);
        g_meff[e] = ssum;
    }
}

// =====================================================================
extern "C" void kernel_launch(void* const* d_in, const int* in_sizes, int n_in,
                              void* d_out, int out_size) {
    const float* x     = (const float*)d_in[0];
    const float* wqkv  = (const float*)d_in[1];
    const float* wdw   = (const float*)d_in[2];
    const float* wproj = (const float*)d_in[3];
    const float* temp  = (const float*)d_in[4];
    float* out = (float*)d_out;

    const int SMEM_QKV  = 2 * 96 * XS2 * 2;      // 27648 B (64-col tiles)
    const int SMEM_PROJ = 2 * 2 * 96 * XS * 2;   // 104448 B (two buffers)
    cudaFuncSetAttribute(qkv_fused_kernel, cudaFuncAttributeMaxDynamicSharedMemorySize, SMEM_QKV);
    cudaFuncSetAttribute(proj_gemm_kernel, cudaFuncAttributeMaxDynamicSharedMemorySize, SMEM_PROJ);

    // 1) qkv = Wqkv @ x — 64-col tiles, 3 CTAs/SM, W L1-resident
    qkv_fused_kernel<<<4096, 192, SMEM_QKV>>>(x, wqkv);
    // 2) depthwise 3x3x3 conv, two halves (v -> bf16 hi/lo)
    dwconv_kernel<<<dim3(4, 8, 144), 256>>>(wdw, 0);
    dwconv_kernel<<<dim3(4, 8, 144), 256>>>(wdw, 144);
    // 3) per-head Gram + norms via tensor cores (slot 3 = profiled)
    gram_kernel<<<dim3(128, 6), 256>>>();
    // 4) parallel reduction of partials
    reduce_kernel<<<54, 256>>>();
    // 5) softmax + fold projection
    finalize_kernel<<<1, 256>>>(temp, wproj);
    // 6) y = Meff @ v — 2 tiles/block, A-frags amortized
    proj_gemm_kernel<<<1024, 192, SMEM_PROJ>>>(out);
}

// round 16
// speedup vs baseline: 1.2781x; 1.0245x over previous
#include <cuda_runtime.h>
#include <cuda_bf16.h>
#include <cstdint>
#include <math.h>

#define NVOX 262144              // 64*64*64
#define NN ((size_t)NVOX)

// ---- scratch (device globals; no allocations allowed) ----
__device__ float g_qkv[288 * NVOX];            // qkv after 1x1 conv
__device__ float g_dw [192 * NVOX];            // q,k after depthwise conv (fp32)
__device__ __nv_bfloat16 g_vh[96 * NVOX];      // v after dwconv, bf16 hi
__device__ __nv_bfloat16 g_vl[96 * NVOX];      // v after dwconv, bf16 lo
__device__ float g_partial[6 * 128 * 288];     // per (head, chunk): 256 gram + 32 norms
__device__ float g_gram[6 * 288];              // reduced gram + norms
__device__ float g_meff[96 * 96];              // W_proj @ blockdiag(attn)

#define XS2 72   // 64-col X smem stride (bf16), 144B rows -> conflict-free

__device__ __forceinline__ unsigned smem_u32(const void* p) {
    return (unsigned)__cvta_generic_to_shared(p);
}
__device__ __forceinline__ void ldsm_x4(unsigned* r, unsigned addr) {
    asm volatile("ldmatrix.sync.aligned.m8n8.x4.shared.b16 {%0,%1,%2,%3}, [%4];"
                 : "=r"(r[0]), "=r"(r[1]), "=r"(r[2]), "=r"(r[3]) : "r"(addr));
}
__device__ __forceinline__ void ldsm_x4t(unsigned* r, unsigned addr) {
    asm volatile("ldmatrix.sync.aligned.m8n8.x4.trans.shared.b16 {%0,%1,%2,%3}, [%4];"
                 : "=r"(r[0]), "=r"(r[1]), "=r"(r[2]), "=r"(r[3]) : "r"(addr));
}
__device__ __forceinline__ void mma16816(float* c, const unsigned* a,
                                         unsigned b0, unsigned b1) {
    asm volatile(
        "mma.sync.aligned.m16n8k16.row.col.f32.bf16.bf16.f32 "
        "{%0,%1,%2,%3}, {%4,%5,%6,%7}, {%8,%9}, {%0,%1,%2,%3};\n"
        : "+f"(c[0]), "+f"(c[1]), "+f"(c[2]), "+f"(c[3])
        : "r"(a[0]), "r"(a[1]), "r"(a[2]), "r"(a[3]), "r"(b0), "r"(b1));
}
__device__ __forceinline__ unsigned pack_hi(float a, float b, unsigned& lo_out) {
    __nv_bfloat162 h = __floats2bfloat162_rn(a, b);
    float2 hf = __bfloat1622float2(h);
    __nv_bfloat162 l = __floats2bfloat162_rn(a - hf.x, b - hf.y);
    lo_out = *(unsigned*)&l;
    return *(unsigned*)&h;
}

// =====================================================================
// A-fragment prep (fp32 W row-pair -> bf16 hi/lo register frags)
// =====================================================================
__device__ __forceinline__ void a_frags(const float* __restrict__ wr0,
                                        const float* __restrict__ wr1, int tt,
                                        unsigned Ah[6][4], unsigned Al[6][4]) {
#pragma unroll
    for (int kc = 0; kc < 6; kc++) {
        float2 w00 = *(const float2*)(wr0 + kc * 16 + tt * 2);
        float2 w10 = *(const float2*)(wr1 + kc * 16 + tt * 2);
        float2 w01 = *(const float2*)(wr0 + kc * 16 + tt * 2 + 8);
        float2 w11 = *(const float2*)(wr1 + kc * 16 + tt * 2 + 8);
        Ah[kc][0] = pack_hi(w00.x, w00.y, Al[kc][0]);
        Ah[kc][1] = pack_hi(w10.x, w10.y, Al[kc][1]);
        Ah[kc][2] = pack_hi(w01.x, w01.y, Al[kc][2]);
        Ah[kc][3] = pack_hi(w11.x, w11.y, Al[kc][3]);
    }
}

// =====================================================================
// 64-col MMA compute core (8 n-fragments)
// =====================================================================
__device__ __forceinline__ void mma_compute64(const __nv_bfloat16* Xh, const __nv_bfloat16* Xl,
                                              const unsigned Ah[6][4], const unsigned Al[6][4],
                                              float* __restrict__ Yo, size_t nb,
                                              int m0, int lane) {
    const int g = lane >> 2, tt = lane & 3;
    const int bl = lane & 15;
    const int bcol = (lane >> 4) << 3;

    float acc[8][4];
#pragma unroll
    for (int nf = 0; nf < 8; nf++)
#pragma unroll
        for (int j = 0; j < 4; j++) acc[nf][j] = 0.f;

#pragma unroll
    for (int kc = 0; kc < 6; kc++) {
        const unsigned ah = smem_u32(&Xh[(kc * 16 + bl) * XS2 + bcol]);
        const unsigned al = smem_u32(&Xl[(kc * 16 + bl) * XS2 + bcol]);
#pragma unroll
        for (int nfp = 0; nfp < 4; nfp++) {
            unsigned bh[4], blo[4];
            ldsm_x4t(bh,  ah + nfp * 32);
            ldsm_x4t(blo, al + nfp * 32);
            mma16816(acc[2 * nfp],     Ah[kc], bh[0],  bh[1]);
            mma16816(acc[2 * nfp],     Ah[kc], blo[0], blo[1]);
            mma16816(acc[2 * nfp],     Al[kc], bh[0],  bh[1]);
            mma16816(acc[2 * nfp + 1], Ah[kc], bh[2],  bh[3]);
            mma16816(acc[2 * nfp + 1], Ah[kc], blo[2], blo[3]);
            mma16816(acc[2 * nfp + 1], Al[kc], bh[2],  bh[3]);
        }
    }

#pragma unroll
    for (int nf = 0; nf < 8; nf++) {
        float* y0 = Yo + (size_t)(m0 + g) * NN + nb + nf * 8 + 2 * tt;
        *(float2*)y0 = make_float2(acc[nf][0], acc[nf][1]);
        float* y1 = Yo + (size_t)(m0 + g + 8) * NN + nb + nf * 8 + 2 * tt;
        *(float2*)y1 = make_float2(acc[nf][2], acc[nf][3]);
    }
}

// =====================================================================
// qkv GEMM — 64-col X tiles (26KB smem), 3 CTAs/SM, W stays L1-resident.
// =====================================================================
__global__ void __launch_bounds__(192, 3)
qkv_fused_kernel(const float* __restrict__ x, const float* __restrict__ wqkv) {
    extern __shared__ __nv_bfloat16 smb[];
    __nv_bfloat16* Xh = smb;
    __nv_bfloat16* Xl = smb + 96 * XS2;

    const int t = threadIdx.x;
    const size_t nb = (size_t)blockIdx.x * 64;

    for (int i = t; i < 96 * 16; i += 192) {
        const int r = i >> 4, c = i & 15;
        float4 v = *(const float4*)(x + (size_t)r * NN + nb + c * 4);
        unsigned l0, l1;
        unsigned h0 = pack_hi(v.x, v.y, l0);
        unsigned h1 = pack_hi(v.z, v.w, l1);
        *(uint2*)&Xh[r * XS2 + c * 4] = make_uint2(h0, h1);
        *(uint2*)&Xl[r * XS2 + c * 4] = make_uint2(l0, l1);
    }
    __syncthreads();

    const int w = t >> 5, lane = t & 31;
    const int m0 = w * 16;
    const int tt = lane & 3;

#pragma unroll 1
    for (int ot = 0; ot < 3; ot++) {
        const float* wr0 = wqkv + (size_t)(ot * 96 + m0 + (lane >> 2)) * 96;
        unsigned Ah[6][4], Al[6][4];
        a_frags(wr0, wr0 + 8 * 96, tt, Ah, Al);
        mma_compute64(Xh, Xl, Ah, Al, g_qkv + (size_t)ot * 96 * NN, nb, m0, lane);
    }
}

// =====================================================================
// proj GEMM — same recipe: 64-col bf16 tiles, 3 CTAs/SM, Meff L1-resident.
// =====================================================================
__global__ void __launch_bounds__(192, 3)
proj_gemm_kernel(float* __restrict__ out) {
    extern __shared__ __nv_bfloat16 smb[];
    __nv_bfloat16* Xh = smb;
    __nv_bfloat16* Xl = smb + 96 * XS2;

    const int t = threadIdx.x;
    const size_t nb = (size_t)blockIdx.x * 64;

    for (int i = t; i < 96 * 8; i += 192) {
        const int r = i >> 3, c = i & 7;
        const size_t go = (size_t)r * NN + nb + c * 8;
        *(uint4*)&Xh[r * XS2 + c * 8] = *(const uint4*)&g_vh[go];
        *(uint4*)&Xl[r * XS2 + c * 8] = *(const uint4*)&g_vl[go];
    }
    __syncthreads();

    const int w = t >> 5, lane = t & 31;
    const int m0 = w * 16;
    const int tt = lane & 3;
    const float* wr0 = g_meff + (size_t)(m0 + (lane >> 2)) * 96;
    unsigned Ah[6][4], Al[6][4];
    a_frags(wr0, wr0 + 8 * 96, tt, Ah, Al);
    mma_compute64(Xh, Xl, Ah, Al, out, nb, m0, lane);
}

// =====================================================================
// Depthwise 3x3x3 conv — scalar; v channels (c>=192) -> bf16 hi/lo.
// =====================================================================
__global__ void __launch_bounds__(256)
dwconv_kernel(const float* __restrict__ wdw, int c0) {
    const int c  = blockIdx.z + c0;
    const int z0 = blockIdx.y * 8;
    const int y0 = blockIdx.x * 16;

    __shared__ float s[10 * 18 * 68];

    float wk[27];
#pragma unroll
    for (int i = 0; i < 27; i++) wk[i] = __ldg(&wdw[c * 27 + i]);

    const float* inc = g_qkv + (size_t)c * NN;
    const int t = threadIdx.x;

    for (int pos = t; pos < 18 * 66; pos += 256) {
        const int iy = pos / 66, ix = pos % 66;
        const int gy = y0 - 1 + iy, gx = ix - 1;
        const bool vyx = ((unsigned)gy < 64u) & ((unsigned)gx < 64u);
        const float* col = inc + ((size_t)gy * 64 + gx);
#pragma unroll
        for (int iz = 0; iz < 10; iz++) {
            const int gz = z0 - 1 + iz;
            float v = 0.f;
            if (vyx && (unsigned)gz < 64u)
                v = col[(size_t)gz * 4096];
            s[(iz * 18 + iy) * 68 + ix] = v;
        }
    }
    __syncthreads();

    const int xx = t & 15;
    const int yy = t >> 4;
    const int x4 = xx * 4;

    float a[8][4];
#pragma unroll
    for (int z = 0; z < 8; z++)
#pragma unroll
        for (int j = 0; j < 4; j++) a[z][j] = 0.f;

#pragma unroll
    for (int p = 0; p < 10; p++) {
        float r[3][6];
#pragma unroll
        for (int ky = 0; ky < 3; ky++) {
            const float* row = &s[(p * 18 + yy + ky) * 68 + x4];
            float4 q  = *(const float4*)row;
            float2 q2 = *(const float2*)(row + 4);
            r[ky][0] = q.x;  r[ky][1] = q.y;  r[ky][2] = q.z;
            r[ky][3] = q.w;  r[ky][4] = q2.x; r[ky][5] = q2.y;
        }
#pragma unroll
        for (int kz = 0; kz < 3; kz++) {
            const int z = p - kz;
            if (z >= 0 && z < 8) {
#pragma unroll
                for (int ky = 0; ky < 3; ky++)
#pragma unroll
                    for (int kx = 0; kx < 3; kx++) {
                        const float wv = wk[kz * 9 + ky * 3 + kx];
#pragma unroll
                        for (int dx = 0; dx < 4; dx++)
                            a[z][dx] = fmaf(wv, r[ky][dx + kx], a[z][dx]);
                    }
            }
        }
    }

    if (c < 192) {
        float* outc = g_dw + (size_t)c * NN;
#pragma unroll
        for (int z = 0; z < 8; z++) {
            *(float4*)&outc[((size_t)(z0 + z) * 64 + (y0 + yy)) * 64 + x4] =
                make_float4(a[z][0], a[z][1], a[z][2], a[z][3]);
        }
    } else {
        const size_t vb = (size_t)(c - 192) * NN;
#pragma unroll
        for (int z = 0; z < 8; z++) {
            const size_t o = vb + ((size_t)(z0 + z) * 64 + (y0 + yy)) * 64 + x4;
            unsigned l0, l1;
            unsigned h0 = pack_hi(a[z][0], a[z][1], l0);
            unsigned h1 = pack_hi(a[z][2], a[z][3], l1);
            *(uint2*)&g_vh[o] = make_uint2(h0, h1);
            *(uint2*)&g_vl[o] = make_uint2(l0, l1);
        }
    }
}

// =====================================================================
// Per-head Gram via tensor cores (unchanged)
// =====================================================================
#define GS 136

__global__ void __launch_bounds__(256)
gram_kernel() {
    const int h = blockIdx.y, chunk = blockIdx.x;
    __shared__ __nv_bfloat16 Qh[16 * GS], Ql[16 * GS], Kh[16 * GS], Kl[16 * GS];
    __shared__ float red[8][256];

    const int t = threadIdx.x;
    const int lane = t & 31, w = t >> 5;
    const int row = t >> 3;
    const int i8  = t & 7;
    const int srow = row & 15;

    const float* nbase = g_dw + (size_t)16 * h * NN + (size_t)chunk * 2048;
    const float* src = (row < 16)
        ? nbase + (size_t)row * NN
        : nbase + (size_t)96 * NN + (size_t)(row - 16) * NN;
    __nv_bfloat16* Dh = (row < 16) ? Qh : Kh;
    __nv_bfloat16* Dl = (row < 16) ? Ql : Kl;

    const int arow = lane & 15;
    const int acol = (lane >> 4) << 3;
    const int bd   = (lane & 7) + ((lane >> 4) << 3);
    const int bko  = ((lane >> 3) & 1) << 3;

    float sq = 0.f;
    float C0[4] = {0.f, 0.f, 0.f, 0.f};
    float C1[4] = {0.f, 0.f, 0.f, 0.f};

    for (int tile = 0; tile < 16; tile++) {
        const int off = tile * 128;
#pragma unroll
        for (int j = 0; j < 4; j++) {
            const int n = off + j * 32 + i8 * 4;
            float4 v = *(const float4*)(src + n);
            unsigned l0, l1;
            unsigned h0 = pack_hi(v.x, v.y, l0);
            unsigned h1 = pack_hi(v.z, v.w, l1);
            const int p = srow * GS + j * 32 + i8 * 4;
            *(uint2*)&Dh[p] = make_uint2(h0, h1);
            *(uint2*)&Dl[p] = make_uint2(l0, l1);
            sq = fmaf(v.x, v.x, fmaf(v.y, v.y, fmaf(v.z, v.z, fmaf(v.w, v.w, sq))));
        }
        __syncthreads();

        unsigned Af[4], Alf[4], Bh[4], Bl[4];
        ldsm_x4(Af,  smem_u32(&Qh[arow * GS + w * 16 + acol]));
        ldsm_x4(Alf, smem_u32(&Ql[arow * GS + w * 16 + acol]));
        ldsm_x4(Bh,  smem_u32(&Kh[bd * GS + w * 16 + bko]));
        ldsm_x4(Bl,  smem_u32(&Kl[bd * GS + w * 16 + bko]));
        mma16816(C0, Af,  Bh[0], Bh[1]);
        mma16816(C1, Af,  Bh[2], Bh[3]);
        mma16816(C0, Af,  Bl[0], Bl[1]);
        mma16816(C1, Af,  Bl[2], Bl[3]);
        mma16816(C0, Alf, Bh[0], Bh[1]);
        mma16816(C1, Alf, Bh[2], Bh[3]);
        __syncthreads();
    }

    const int cr = lane >> 2, cc2 = (lane & 3) * 2;
    red[w][cr * 16 + cc2]           = C0[0];
    red[w][cr * 16 + cc2 + 1]       = C0[1];
    red[w][(cr + 8) * 16 + cc2]     = C0[2];
    red[w][(cr + 8) * 16 + cc2 + 1] = C0[3];
    red[w][cr * 16 + 8 + cc2]           = C1[0];
    red[w][cr * 16 + 8 + cc2 + 1]       = C1[1];
    red[w][(cr + 8) * 16 + 8 + cc2]     = C1[2];
    red[w][(cr + 8) * 16 + 8 + cc2 + 1] = C1[3];
    __syncthreads();

    float acc = 0.f;
#pragma unroll
    for (int ww = 0; ww < 8; ww++) acc += red[ww][t];
    const size_t pb = ((size_t)h * 128 + chunk) * 288;
    g_partial[pb + t] = acc;

    sq += __shfl_xor_sync(0xffffffff, sq, 1);
    sq += __shfl_xor_sync(0xffffffff, sq, 2);
    sq += __shfl_xor_sync(0xffffffff, sq, 4);
    if (i8 == 0) g_partial[pb + 256 + row] = sq;
}

__global__ void __launch_bounds__(256)
reduce_kernel() {
    const int h = blockIdx.x / 9, grp = blockIdx.x % 9;
    const int t = threadIdx.x;
    const int e = grp * 32 + (t & 31);
    const int sub = t >> 5;
    float s = 0.f;
    const int ch0 = sub * 16;
    for (int ch = ch0; ch < ch0 + 16; ch++)
        s += g_partial[((size_t)h * 128 + ch) * 288 + e];
    __shared__ float sm[256];
    sm[t] = s; __syncthreads();
    if (t < 128) sm[t] += sm[t + 128]; __syncthreads();
    if (t < 64)  sm[t] += sm[t + 64];  __syncthreads();
    if (t < 32)  g_gram[h * 288 + e] = sm[t] + sm[t + 32];
}

__global__ void __launch_bounds__(256)
finalize_kernel(const float* __restrict__ temp, const float* __restrict__ wproj) {
    __shared__ float A[6 * 256];
    __shared__ float qn[6 * 16], kn[6 * 16];
    __shared__ float attn[6 * 256];
    const int t = threadIdx.x;

    for (int e = t; e < 1536; e += 256) {
        const int h = e >> 8, idx = e & 255;
        A[e] = g_gram[h * 288 + idx];
    }
    if (t < 192) {
        const int h = t / 32, r = t % 32;
        float nv = fmaxf(sqrtf(g_gram[h * 288 + 256 + r]), 1e-12f);
        if (r < 16) qn[h * 16 + r] = nv;
        else        kn[h * 16 + (r - 16)] = nv;
    }
    __syncthreads();

    if (t < 96) {
        const int h = t >> 4, c = t & 15;
        const float tp = temp[h];
        float l[16];
        float mx = -1e30f;
#pragma unroll
        for (int d = 0; d < 16; d++) {
            float v = A[h * 256 + c * 16 + d] / (qn[h * 16 + c] * kn[h * 16 + d]) * tp;
            l[d] = v;
            mx = fmaxf(mx, v);
        }
        float ssum = 0.f;
#pragma unroll
        for (int d = 0; d < 16; d++) { l[d] = expf(l[d] - mx); ssum += l[d]; }
        const float inv = 1.f / ssum;
#pragma unroll
        for (int d = 0; d < 16; d++) attn[h * 256 + c * 16 + d] = l[d] * inv;
    }
    __syncthreads();

    for (int e = t; e < 9216; e += 256) {
        const int o = e / 96, g = e % 96;
        const int h = g >> 4, d = g & 15;
        float ssum = 0.f;
#pragma unroll
        for (int c = 0; c < 16; c++)
            ssum = fmaf(wproj[o * 96 + 16 * h + c], attn[h * 256 + c * 16 + d], ssum);
        g_meff[e] = ssum;
    }
}

// =====================================================================
extern "C" void kernel_launch(void* const* d_in, const int* in_sizes, int n_in,
                              void* d_out, int out_size) {
    const float* x     = (const float*)d_in[0];
    const float* wqkv  = (const float*)d_in[1];
    const float* wdw   = (const float*)d_in[2];
    const float* wproj = (const float*)d_in[3];
    const float* temp  = (const float*)d_in[4];
    float* out = (float*)d_out;

    const int SMEM_64 = 2 * 96 * XS2 * 2;   // 27648 B (64-col tiles)
    cudaFuncSetAttribute(qkv_fused_kernel, cudaFuncAttributeMaxDynamicSharedMemorySize, SMEM_64);
    cudaFuncSetAttribute(proj_gemm_kernel, cudaFuncAttributeMaxDynamicSharedMemorySize, SMEM_64);

    // 1) qkv = Wqkv @ x — 64-col tiles, 3 CTAs/SM, W L1-resident
    qkv_fused_kernel<<<4096, 192, SMEM_64>>>(x, wqkv);
    // 2) depthwise 3x3x3 conv, two halves (v -> bf16 hi/lo)
    dwconv_kernel<<<dim3(4, 8, 144), 256>>>(wdw, 0);
    dwconv_kernel<<<dim3(4, 8, 144), 256>>>(wdw, 144);
    // 3) per-head Gram + norms via tensor cores (slot 3 = profiled)
    gram_kernel<<<dim3(128, 6), 256>>>();
    // 4) parallel reduction of partials
    reduce_kernel<<<54, 256>>>();
    // 5) softmax + fold projection
    finalize_kernel<<<1, 256>>>(temp, wproj);
    // 6) y = Meff @ v — 64-col tiles, 3 CTAs/SM, Meff L1-resident
    proj_gemm_kernel<<<4096, 192, SMEM_64>>>(out);
}

// round 17
// speedup vs baseline: 1.3167x; 1.0302x over previous
#include <cuda_runtime.h>
#include <cuda_bf16.h>
#include <cstdint>
#include <math.h>

#define NVOX 262144              // 64*64*64
#define NN ((size_t)NVOX)

// ---- scratch (device globals; no allocations allowed) ----
__device__ float g_qkv[288 * NVOX];            // qkv after 1x1 conv
__device__ float g_dw [192 * NVOX];            // q,k after depthwise conv (fp32)
__device__ __nv_bfloat16 g_vh[96 * NVOX];      // v after dwconv, bf16 hi
__device__ __nv_bfloat16 g_vl[96 * NVOX];      // v after dwconv, bf16 lo
__device__ float g_partial[6 * 128 * 288];     // per (head, chunk): 256 gram + 32 norms
__device__ float g_gram[6 * 288];              // reduced gram + norms
__device__ float g_meff[96 * 96];              // W_proj @ blockdiag(attn)

#define XS2 72   // 64-col X smem stride (bf16), 144B rows -> conflict-free

__device__ __forceinline__ unsigned smem_u32(const void* p) {
    return (unsigned)__cvta_generic_to_shared(p);
}
__device__ __forceinline__ void ldsm_x4(unsigned* r, unsigned addr) {
    asm volatile("ldmatrix.sync.aligned.m8n8.x4.shared.b16 {%0,%1,%2,%3}, [%4];"
                 : "=r"(r[0]), "=r"(r[1]), "=r"(r[2]), "=r"(r[3]) : "r"(addr));
}
__device__ __forceinline__ void ldsm_x4t(unsigned* r, unsigned addr) {
    asm volatile("ldmatrix.sync.aligned.m8n8.x4.trans.shared.b16 {%0,%1,%2,%3}, [%4];"
                 : "=r"(r[0]), "=r"(r[1]), "=r"(r[2]), "=r"(r[3]) : "r"(addr));
}
__device__ __forceinline__ void mma16816(float* c, const unsigned* a,
                                         unsigned b0, unsigned b1) {
    asm volatile(
        "mma.sync.aligned.m16n8k16.row.col.f32.bf16.bf16.f32 "
        "{%0,%1,%2,%3}, {%4,%5,%6,%7}, {%8,%9}, {%0,%1,%2,%3};\n"
        : "+f"(c[0]), "+f"(c[1]), "+f"(c[2]), "+f"(c[3])
        : "r"(a[0]), "r"(a[1]), "r"(a[2]), "r"(a[3]), "r"(b0), "r"(b1));
}
__device__ __forceinline__ unsigned pack_hi(float a, float b, unsigned& lo_out) {
    __nv_bfloat162 h = __floats2bfloat162_rn(a, b);
    float2 hf = __bfloat1622float2(h);
    __nv_bfloat162 l = __floats2bfloat162_rn(a - hf.x, b - hf.y);
    lo_out = *(unsigned*)&l;
    return *(unsigned*)&h;
}

// =====================================================================
// A-fragment prep (fp32 W row-pair -> bf16 hi/lo register frags)
// =====================================================================
__device__ __forceinline__ void a_frags(const float* __restrict__ wr0,
                                        const float* __restrict__ wr1, int tt,
                                        unsigned Ah[6][4], unsigned Al[6][4]) {
#pragma unroll
    for (int kc = 0; kc < 6; kc++) {
        float2 w00 = *(const float2*)(wr0 + kc * 16 + tt * 2);
        float2 w10 = *(const float2*)(wr1 + kc * 16 + tt * 2);
        float2 w01 = *(const float2*)(wr0 + kc * 16 + tt * 2 + 8);
        float2 w11 = *(const float2*)(wr1 + kc * 16 + tt * 2 + 8);
        Ah[kc][0] = pack_hi(w00.x, w00.y, Al[kc][0]);
        Ah[kc][1] = pack_hi(w10.x, w10.y, Al[kc][1]);
        Ah[kc][2] = pack_hi(w01.x, w01.y, Al[kc][2]);
        Ah[kc][3] = pack_hi(w11.x, w11.y, Al[kc][3]);
    }
}

// =====================================================================
// 64-col MMA compute core (8 n-fragments)
// =====================================================================
__device__ __forceinline__ void mma_compute64(const __nv_bfloat16* Xh, const __nv_bfloat16* Xl,
                                              const unsigned Ah[6][4], const unsigned Al[6][4],
                                              float* __restrict__ Yo, size_t nb,
                                              int m0, int lane) {
    const int g = lane >> 2, tt = lane & 3;
    const int bl = lane & 15;
    const int bcol = (lane >> 4) << 3;

    float acc[8][4];
#pragma unroll
    for (int nf = 0; nf < 8; nf++)
#pragma unroll
        for (int j = 0; j < 4; j++) acc[nf][j] = 0.f;

#pragma unroll
    for (int kc = 0; kc < 6; kc++) {
        const unsigned ah = smem_u32(&Xh[(kc * 16 + bl) * XS2 + bcol]);
        const unsigned al = smem_u32(&Xl[(kc * 16 + bl) * XS2 + bcol]);
#pragma unroll
        for (int nfp = 0; nfp < 4; nfp++) {
            unsigned bh[4], blo[4];
            ldsm_x4t(bh,  ah + nfp * 32);
            ldsm_x4t(blo, al + nfp * 32);
            mma16816(acc[2 * nfp],     Ah[kc], bh[0],  bh[1]);
            mma16816(acc[2 * nfp],     Ah[kc], blo[0], blo[1]);
            mma16816(acc[2 * nfp],     Al[kc], bh[0],  bh[1]);
            mma16816(acc[2 * nfp + 1], Ah[kc], bh[2],  bh[3]);
            mma16816(acc[2 * nfp + 1], Ah[kc], blo[2], blo[3]);
            mma16816(acc[2 * nfp + 1], Al[kc], bh[2],  bh[3]);
        }
    }

#pragma unroll
    for (int nf = 0; nf < 8; nf++) {
        float* y0 = Yo + (size_t)(m0 + g) * NN + nb + nf * 8 + 2 * tt;
        *(float2*)y0 = make_float2(acc[nf][0], acc[nf][1]);
        float* y1 = Yo + (size_t)(m0 + g + 8) * NN + nb + nf * 8 + 2 * tt;
        *(float2*)y1 = make_float2(acc[nf][2], acc[nf][3]);
    }
}

// =====================================================================
// qkv GEMM — 64-col X tiles (26KB smem), 3 CTAs/SM, W stays L1-resident.
// =====================================================================
__global__ void __launch_bounds__(192, 3)
qkv_fused_kernel(const float* __restrict__ x, const float* __restrict__ wqkv) {
    extern __shared__ __nv_bfloat16 smb[];
    __nv_bfloat16* Xh = smb;
    __nv_bfloat16* Xl = smb + 96 * XS2;

    const int t = threadIdx.x;
    const size_t nb = (size_t)blockIdx.x * 64;

    for (int i = t; i < 96 * 16; i += 192) {
        const int r = i >> 4, c = i & 15;
        float4 v = *(const float4*)(x + (size_t)r * NN + nb + c * 4);
        unsigned l0, l1;
        unsigned h0 = pack_hi(v.x, v.y, l0);
        unsigned h1 = pack_hi(v.z, v.w, l1);
        *(uint2*)&Xh[r * XS2 + c * 4] = make_uint2(h0, h1);
        *(uint2*)&Xl[r * XS2 + c * 4] = make_uint2(l0, l1);
    }
    __syncthreads();

    const int w = t >> 5, lane = t & 31;
    const int m0 = w * 16;
    const int tt = lane & 3;

#pragma unroll 1
    for (int ot = 0; ot < 3; ot++) {
        const float* wr0 = wqkv + (size_t)(ot * 96 + m0 + (lane >> 2)) * 96;
        unsigned Ah[6][4], Al[6][4];
        a_frags(wr0, wr0 + 8 * 96, tt, Ah, Al);
        mma_compute64(Xh, Xl, Ah, Al, g_qkv + (size_t)ot * 96 * NN, nb, m0, lane);
    }
}

// =====================================================================
// proj GEMM — 64-col bf16 tiles, 4 CTAs/SM (Meff=36KB stays L1-resident).
// =====================================================================
__global__ void __launch_bounds__(192, 4)
proj_gemm_kernel(float* __restrict__ out) {
    extern __shared__ __nv_bfloat16 smb[];
    __nv_bfloat16* Xh = smb;
    __nv_bfloat16* Xl = smb + 96 * XS2;

    const int t = threadIdx.x;
    const size_t nb = (size_t)blockIdx.x * 64;

    for (int i = t; i < 96 * 8; i += 192) {
        const int r = i >> 3, c = i & 7;
        const size_t go = (size_t)r * NN + nb + c * 8;
        *(uint4*)&Xh[r * XS2 + c * 8] = *(const uint4*)&g_vh[go];
        *(uint4*)&Xl[r * XS2 + c * 8] = *(const uint4*)&g_vl[go];
    }
    __syncthreads();

    const int w = t >> 5, lane = t & 31;
    const int m0 = w * 16;
    const int tt = lane & 3;
    const float* wr0 = g_meff + (size_t)(m0 + (lane >> 2)) * 96;
    unsigned Ah[6][4], Al[6][4];
    a_frags(wr0, wr0 + 8 * 96, tt, Ah, Al);
    mma_compute64(Xh, Xl, Ah, Al, out, nb, m0, lane);
}

// =====================================================================
// Depthwise 3x3x3 conv — scalar; v channels (c>=192) -> bf16 hi/lo.
// Single launch, all 288 channels.
// =====================================================================
__global__ void __launch_bounds__(256)
dwconv_kernel(const float* __restrict__ wdw) {
    const int c  = blockIdx.z;
    const int z0 = blockIdx.y * 8;
    const int y0 = blockIdx.x * 16;

    __shared__ float s[10 * 18 * 68];

    float wk[27];
#pragma unroll
    for (int i = 0; i < 27; i++) wk[i] = __ldg(&wdw[c * 27 + i]);

    const float* inc = g_qkv + (size_t)c * NN;
    const int t = threadIdx.x;

    for (int pos = t; pos < 18 * 66; pos += 256) {
        const int iy = pos / 66, ix = pos % 66;
        const int gy = y0 - 1 + iy, gx = ix - 1;
        const bool vyx = ((unsigned)gy < 64u) & ((unsigned)gx < 64u);
        const float* col = inc + ((size_t)gy * 64 + gx);
#pragma unroll
        for (int iz = 0; iz < 10; iz++) {
            const int gz = z0 - 1 + iz;
            float v = 0.f;
            if (vyx && (unsigned)gz < 64u)
                v = col[(size_t)gz * 4096];
            s[(iz * 18 + iy) * 68 + ix] = v;
        }
    }
    __syncthreads();

    const int xx = t & 15;
    const int yy = t >> 4;
    const int x4 = xx * 4;

    float a[8][4];
#pragma unroll
    for (int z = 0; z < 8; z++)
#pragma unroll
        for (int j = 0; j < 4; j++) a[z][j] = 0.f;

#pragma unroll
    for (int p = 0; p < 10; p++) {
        float r[3][6];
#pragma unroll
        for (int ky = 0; ky < 3; ky++) {
            const float* row = &s[(p * 18 + yy + ky) * 68 + x4];
            float4 q  = *(const float4*)row;
            float2 q2 = *(const float2*)(row + 4);
            r[ky][0] = q.x;  r[ky][1] = q.y;  r[ky][2] = q.z;
            r[ky][3] = q.w;  r[ky][4] = q2.x; r[ky][5] = q2.y;
        }
#pragma unroll
        for (int kz = 0; kz < 3; kz++) {
            const int z = p - kz;
            if (z >= 0 && z < 8) {
#pragma unroll
                for (int ky = 0; ky < 3; ky++)
#pragma unroll
                    for (int kx = 0; kx < 3; kx++) {
                        const float wv = wk[kz * 9 + ky * 3 + kx];
#pragma unroll
                        for (int dx = 0; dx < 4; dx++)
                            a[z][dx] = fmaf(wv, r[ky][dx + kx], a[z][dx]);
                    }
            }
        }
    }

    if (c < 192) {
        float* outc = g_dw + (size_t)c * NN;
#pragma unroll
        for (int z = 0; z < 8; z++) {
            *(float4*)&outc[((size_t)(z0 + z) * 64 + (y0 + yy)) * 64 + x4] =
                make_float4(a[z][0], a[z][1], a[z][2], a[z][3]);
        }
    } else {
        const size_t vb = (size_t)(c - 192) * NN;
#pragma unroll
        for (int z = 0; z < 8; z++) {
            const size_t o = vb + ((size_t)(z0 + z) * 64 + (y0 + yy)) * 64 + x4;
            unsigned l0, l1;
            unsigned h0 = pack_hi(a[z][0], a[z][1], l0);
            unsigned h1 = pack_hi(a[z][2], a[z][3], l1);
            *(uint2*)&g_vh[o] = make_uint2(h0, h1);
            *(uint2*)&g_vl[o] = make_uint2(l0, l1);
        }
    }
}

// =====================================================================
// Per-head Gram via tensor cores (unchanged)
// =====================================================================
#define GS 136

__global__ void __launch_bounds__(256)
gram_kernel() {
    const int h = blockIdx.y, chunk = blockIdx.x;
    __shared__ __nv_bfloat16 Qh[16 * GS], Ql[16 * GS], Kh[16 * GS], Kl[16 * GS];
    __shared__ float red[8][256];

    const int t = threadIdx.x;
    const int lane = t & 31, w = t >> 5;
    const int row = t >> 3;
    const int i8  = t & 7;
    const int srow = row & 15;

    const float* nbase = g_dw + (size_t)16 * h * NN + (size_t)chunk * 2048;
    const float* src = (row < 16)
        ? nbase + (size_t)row * NN
        : nbase + (size_t)96 * NN + (size_t)(row - 16) * NN;
    __nv_bfloat16* Dh = (row < 16) ? Qh : Kh;
    __nv_bfloat16* Dl = (row < 16) ? Ql : Kl;

    const int arow = lane & 15;
    const int acol = (lane >> 4) << 3;
    const int bd   = (lane & 7) + ((lane >> 4) << 3);
    const int bko  = ((lane >> 3) & 1) << 3;

    float sq = 0.f;
    float C0[4] = {0.f, 0.f, 0.f, 0.f};
    float C1[4] = {0.f, 0.f, 0.f, 0.f};

    for (int tile = 0; tile < 16; tile++) {
        const int off = tile * 128;
#pragma unroll
        for (int j = 0; j < 4; j++) {
            const int n = off + j * 32 + i8 * 4;
            float4 v = *(const float4*)(src + n);
            unsigned l0, l1;
            unsigned h0 = pack_hi(v.x, v.y, l0);
            unsigned h1 = pack_hi(v.z, v.w, l1);
            const int p = srow * GS + j * 32 + i8 * 4;
            *(uint2*)&Dh[p] = make_uint2(h0, h1);
            *(uint2*)&Dl[p] = make_uint2(l0, l1);
            sq = fmaf(v.x, v.x, fmaf(v.y, v.y, fmaf(v.z, v.z, fmaf(v.w, v.w, sq))));
        }
        __syncthreads();

        unsigned Af[4], Alf[4], Bh[4], Bl[4];
        ldsm_x4(Af,  smem_u32(&Qh[arow * GS + w * 16 + acol]));
        ldsm_x4(Alf, smem_u32(&Ql[arow * GS + w * 16 + acol]));
        ldsm_x4(Bh,  smem_u32(&Kh[bd * GS + w * 16 + bko]));
        ldsm_x4(Bl,  smem_u32(&Kl[bd * GS + w * 16 + bko]));
        mma16816(C0, Af,  Bh[0], Bh[1]);
        mma16816(C1, Af,  Bh[2], Bh[3]);
        mma16816(C0, Af,  Bl[0], Bl[1]);
        mma16816(C1, Af,  Bl[2], Bl[3]);
        mma16816(C0, Alf, Bh[0], Bh[1]);
        mma16816(C1, Alf, Bh[2], Bh[3]);
        __syncthreads();
    }

    const int cr = lane >> 2, cc2 = (lane & 3) * 2;
    red[w][cr * 16 + cc2]           = C0[0];
    red[w][cr * 16 + cc2 + 1]       = C0[1];
    red[w][(cr + 8) * 16 + cc2]     = C0[2];
    red[w][(cr + 8) * 16 + cc2 + 1] = C0[3];
    red[w][cr * 16 + 8 + cc2]           = C1[0];
    red[w][cr * 16 + 8 + cc2 + 1]       = C1[1];
    red[w][(cr + 8) * 16 + 8 + cc2]     = C1[2];
    red[w][(cr + 8) * 16 + 8 + cc2 + 1] = C1[3];
    __syncthreads();

    float acc = 0.f;
#pragma unroll
    for (int ww = 0; ww < 8; ww++) acc += red[ww][t];
    const size_t pb = ((size_t)h * 128 + chunk) * 288;
    g_partial[pb + t] = acc;

    sq += __shfl_xor_sync(0xffffffff, sq, 1);
    sq += __shfl_xor_sync(0xffffffff, sq, 2);
    sq += __shfl_xor_sync(0xffffffff, sq, 4);
    if (i8 == 0) g_partial[pb + 256 + row] = sq;
}

__global__ void __launch_bounds__(256)
reduce_kernel() {
    const int h = blockIdx.x / 9, grp = blockIdx.x % 9;
    const int t = threadIdx.x;
    const int e = grp * 32 + (t & 31);
    const int sub = t >> 5;
    float s = 0.f;
    const int ch0 = sub * 16;
    for (int ch = ch0; ch < ch0 + 16; ch++)
        s += g_partial[((size_t)h * 128 + ch) * 288 + e];
    __shared__ float sm[256];
    sm[t] = s; __syncthreads();
    if (t < 128) sm[t] += sm[t + 128]; __syncthreads();
    if (t < 64)  sm[t] += sm[t + 64];  __syncthreads();
    if (t < 32)  g_gram[h * 288 + e] = sm[t] + sm[t + 32];
}

__global__ void __launch_bounds__(256)
finalize_kernel(const float* __restrict__ temp, const float* __restrict__ wproj) {
    __shared__ float A[6 * 256];
    __shared__ float qn[6 * 16], kn[6 * 16];
    __shared__ float attn[6 * 256];
    const int t = threadIdx.x;

    for (int e = t; e < 1536; e += 256) {
        const int h = e >> 8, idx = e & 255;
        A[e] = g_gram[h * 288 + idx];
    }
    if (t < 192) {
        const int h = t / 32, r = t % 32;
        float nv = fmaxf(sqrtf(g_gram[h * 288 + 256 + r]), 1e-12f);
        if (r < 16) qn[h * 16 + r] = nv;
        else        kn[h * 16 + (r - 16)] = nv;
    }
    __syncthreads();

    if (t < 96) {
        const int h = t >> 4, c = t & 15;
        const float tp = temp[h];
        float l[16];
        float mx = -1e30f;
#pragma unroll
        for (int d = 0; d < 16; d++) {
            float v = A[h * 256 + c * 16 + d] / (qn[h * 16 + c] * kn[h * 16 + d]) * tp;
            l[d] = v;
            mx = fmaxf(mx, v);
        }
        float ssum = 0.f;
#pragma unroll
        for (int d = 0; d < 16; d++) { l[d] = expf(l[d] - mx); ssum += l[d]; }
        const float inv = 1.f / ssum;
#pragma unroll
        for (int d = 0; d < 16; d++) attn[h * 256 + c * 16 + d] = l[d] * inv;
    }
    __syncthreads();

    for (int e = t; e < 9216; e += 256) {
        const int o = e / 96, g = e % 96;
        const int h = g >> 4, d = g & 15;
        float ssum = 0.f;
#pragma unroll
        for (int c = 0; c < 16; c++)
            ssum = fmaf(wproj[o * 96 + 16 * h + c], attn[h * 256 + c * 16 + d], ssum);
        g_meff[e] = ssum;
    }
}

// =====================================================================
extern "C" void kernel_launch(void* const* d_in, const int* in_sizes, int n_in,
                              void* d_out, int out_size) {
    const float* x     = (const float*)d_in[0];
    const float* wqkv  = (const float*)d_in[1];
    const float* wdw   = (const float*)d_in[2];
    const float* wproj = (const float*)d_in[3];
    const float* temp  = (const float*)d_in[4];
    float* out = (float*)d_out;

    const int SMEM_64 = 2 * 96 * XS2 * 2;   // 27648 B (64-col tiles)
    cudaFuncSetAttribute(qkv_fused_kernel, cudaFuncAttributeMaxDynamicSharedMemorySize, SMEM_64);
    cudaFuncSetAttribute(proj_gemm_kernel, cudaFuncAttributeMaxDynamicSharedMemorySize, SMEM_64);

    // 1) qkv = Wqkv @ x — 64-col tiles, 3 CTAs/SM, W L1-resident
    qkv_fused_kernel<<<4096, 192, SMEM_64>>>(x, wqkv);
    // 2) depthwise 3x3x3 conv — single launch, v -> bf16 hi/lo
    dwconv_kernel<<<dim3(4, 8, 288), 256>>>(wdw);
    // 3) per-head Gram + norms via tensor cores
    gram_kernel<<<dim3(128, 6), 256>>>();
    // 4) parallel reduction of partials
    reduce_kernel<<<54, 256>>>();
    // 5) softmax + fold projection
    finalize_kernel<<<1, 256>>>(temp, wproj);
    // 6) y = Meff @ v — 64-col tiles, 4 CTAs/SM, Meff L1-resident
    proj_gemm_kernel<<<4096, 192, SMEM_64>>>(out);
}